// round 6
// baseline (speedup 1.0000x reference)
#include <cuda_runtime.h>
#include <cuda_bf16.h>
#include <math.h>
#include <stdint.h>

// ---------------- problem constants ----------------
#define BB 2
#define SS 1024
#define UU 1024
#define HH 16
#define DD 64
#define NT 32000
#define MEMLEN 576
#define FFD 4096
#define KLEN 1600   // MEM + S
#define VOCAB 1024

typedef __nv_bfloat16 bf16;

// ---------------- scratch (device globals; no allocation allowed) ----------------
__device__ float g_ac  [(size_t)BB*HH*SS*KLEN];
__device__ float g_ar  [(size_t)BB*HH*SS*KLEN];
__device__ float g_x   [(size_t)BB*SS*UU];
__device__ float g_tmp [(size_t)BB*SS*UU];
__device__ float g_h1  [(size_t)BB*SS*UU];
__device__ float g_h2  [(size_t)BB*SS*UU];

__device__ bf16 g_xh   [(size_t)BB*SS*UU],   g_xl   [(size_t)BB*SS*UU];
__device__ bf16 g_fullh[(size_t)BB*KLEN*UU], g_fulll[(size_t)BB*KLEN*UU];
__device__ bf16 g_relh [(size_t)KLEN*UU],    g_rell [(size_t)KLEN*UU];
__device__ bf16 g_qch  [(size_t)BB*SS*UU],   g_qcl  [(size_t)BB*SS*UU];
__device__ bf16 g_qrh  [(size_t)BB*SS*UU],   g_qrl  [(size_t)BB*SS*UU];
__device__ bf16 g_kvh  [(size_t)BB*KLEN*2*UU], g_kvl [(size_t)BB*KLEN*2*UU];
__device__ bf16 g_rh   [(size_t)KLEN*UU],    g_rl   [(size_t)KLEN*UU];
__device__ bf16 g_ph   [(size_t)BB*HH*SS*KLEN], g_pl [(size_t)BB*HH*SS*KLEN];
__device__ bf16 g_vth  [(size_t)BB*HH*DD*KLEN], g_vtl[(size_t)BB*HH*DD*KLEN];
__device__ bf16 g_ctxh [(size_t)BB*SS*UU],   g_ctxl [(size_t)BB*SS*UU];
__device__ bf16 g_h1h  [(size_t)BB*SS*UU],   g_h1l  [(size_t)BB*SS*UU];
__device__ bf16 g_h2h  [(size_t)BB*SS*UU],   g_h2l  [(size_t)BB*SS*UU];
__device__ bf16 g_ffh  [(size_t)BB*SS*FFD],  g_ffl  [(size_t)BB*SS*FFD];
__device__ bf16 g_WqTh [(size_t)UU*UU],    g_WqTl [(size_t)UU*UU];
__device__ bf16 g_WkvTh[(size_t)2*UU*UU],  g_WkvTl[(size_t)2*UU*UU];
__device__ bf16 g_WrTh [(size_t)UU*UU],    g_WrTl [(size_t)UU*UU];
__device__ bf16 g_WoTh [(size_t)UU*UU],    g_WoTl [(size_t)UU*UU];
__device__ bf16 g_W1Th [(size_t)FFD*UU],   g_W1Tl [(size_t)FFD*UU];
__device__ bf16 g_W2Th [(size_t)UU*FFD],   g_W2Tl [(size_t)UU*FFD];
__device__ bf16 g_WoutTh[(size_t)NT*UU],   g_WoutTl[(size_t)NT*UU];

// ---------------- helpers ----------------
__device__ __forceinline__ uint32_t smem_u32(const void* p) {
    uint32_t a;
    asm("{ .reg .u64 t; cvta.to.shared.u64 t, %1; cvt.u32.u64 %0, t; }" : "=r"(a) : "l"(p));
    return a;
}
__device__ __forceinline__ void split_val(float v, bf16& h, bf16& l) {
    h = __float2bfloat16(v);
    l = __float2bfloat16(v - __bfloat162float(h));
}
__device__ __forceinline__ void cp16(uint32_t dst, const void* src) {
    asm volatile("cp.async.cg.shared.global [%0], [%1], 16;" :: "r"(dst), "l"(src));
}
__device__ __forceinline__ void ldx4(uint32_t* r, uint32_t addr) {
    asm volatile("ldmatrix.sync.aligned.m8n8.x4.shared.b16 {%0,%1,%2,%3}, [%4];"
                 : "=r"(r[0]), "=r"(r[1]), "=r"(r[2]), "=r"(r[3]) : "r"(addr));
}
__device__ __forceinline__ void ldx2(uint32_t* r, uint32_t addr) {
    asm volatile("ldmatrix.sync.aligned.m8n8.x2.shared.b16 {%0,%1}, [%2];"
                 : "=r"(r[0]), "=r"(r[1]) : "r"(addr));
}
__device__ __forceinline__ void mma16816(float* c, const uint32_t* a, const uint32_t* b) {
    asm volatile("mma.sync.aligned.m16n8k16.row.col.f32.bf16.bf16.f32 "
                 "{%0,%1,%2,%3}, {%4,%5,%6,%7}, {%8,%9}, {%0,%1,%2,%3};"
                 : "+f"(c[0]), "+f"(c[1]), "+f"(c[2]), "+f"(c[3])
                 : "r"(a[0]), "r"(a[1]), "r"(a[2]), "r"(a[3]), "r"(b[0]), "r"(b[1]));
}

// ---------------- generalized HMMA split-bf16 GEMM ----------------
// C[M,N](ldc) = (Ah+Al)[M,K](lda) @ (Bh+Bl)[N,K](ldb)^T + bias
// 3-pass split: hh + hl + lh, fp32 accum.
// GRID: blockIdx.x = M-tile (x-major scheduling => concurrent CTAs share one
//       N-strip, giving B-tile reuse through L2), blockIdx.y = N-tile,
//       blockIdx.z = batch (z1 = z/Z2, z2 = z%Z2).
// OUT: 0 = fp32 C; 1 = split bf16 Ch/Cl; 2 = relu + split;
//      3 = dual-bias split: Ch/Cl = split(v+bias2), Dh/Dl = split(v+bias3).
template<int BN, int OUT>
__global__ __launch_bounds__(256)
void hgemm(const bf16* __restrict__ Ah, const bf16* __restrict__ Al,
           const bf16* __restrict__ Bh, const bf16* __restrict__ Bl,
           float* __restrict__ C, bf16* __restrict__ Ch, bf16* __restrict__ Cl,
           bf16* __restrict__ Dh, bf16* __restrict__ Dl,
           const float* __restrict__ bias,
           const float* __restrict__ bias2, const float* __restrict__ bias3,
           int M, int N, int K, int lda, int ldb, int ldc, int Z2,
           long long sA1, long long sA2, long long sB1, long long sB2,
           long long sC1, long long sC2)
{
    constexpr int STAGE = 8192 + 2 * BN * 32;
    constexpr int MT = (BN == 128) ? 4 : 2;
    __shared__ __align__(128) char sm[3 * STAGE];
    const uint32_t smb = smem_u32(sm);
    const int tid = threadIdx.x, wid = tid >> 5, lane = tid & 31;
    const int m0 = blockIdx.x * 128, n0 = blockIdx.y * BN;
    const int m_w = (BN == 128) ? (wid & 1) * 64 : (wid & 3) * 32;
    const int n_w = (BN == 128) ? (wid >> 1) * 32 : (wid >> 2) * 32;

    const int z = blockIdx.z;
    const int z1 = z / Z2, z2 = z - z1 * Z2;
    Ah += z1 * sA1 + z2 * sA2;  Al += z1 * sA1 + z2 * sA2;
    Bh += z1 * sB1 + z2 * sB2;  Bl += z1 * sB1 + z2 * sB2;
    const long long cbase = z1 * sC1 + z2 * sC2;

    const int lr = tid >> 1, lc = tid & 1;
    const uint32_t so = (uint32_t)(lr * 32 + ((lc ^ ((lr >> 2) & 1)) << 4));
    const int ga = min(m0 + lr, M - 1);
    const long long aoff = (long long)ga * lda + lc * 8;
    const bool bdo = (BN == 128) || (tid < 128);
    const int gb = min(n0 + lr, N - 1);
    const long long boff = (long long)gb * ldb + lc * 8;

    float acc[MT][4][4];
    #pragma unroll
    for (int i = 0; i < MT; i++)
        #pragma unroll
        for (int j = 0; j < 4; j++)
            #pragma unroll
            for (int k = 0; k < 4; k++) acc[i][j][k] = 0.f;

    const int NC = K / 16;

    #pragma unroll
    for (int pc = 0; pc < 2; pc++) {
        const uint32_t st = smb + pc * STAGE;
        cp16(st + so,        Ah + aoff + pc * 16);
        cp16(st + 4096 + so, Al + aoff + pc * 16);
        if (bdo) {
            cp16(st + 8192 + so,           Bh + boff + pc * 16);
            cp16(st + 8192 + BN * 32 + so, Bl + boff + pc * 16);
        }
        asm volatile("cp.async.commit_group;");
    }

    const int rr = lane & 15, ccq = lane >> 4;
    const int rb = lane & 7,  cb = (lane >> 3) & 1;

    for (int c = 0; c < NC; c++) {
        if (c + 2 < NC) {
            const uint32_t st = smb + ((c + 2) % 3) * STAGE;
            const long long k0 = (long long)(c + 2) * 16;
            cp16(st + so,        Ah + aoff + k0);
            cp16(st + 4096 + so, Al + aoff + k0);
            if (bdo) {
                cp16(st + 8192 + so,           Bh + boff + k0);
                cp16(st + 8192 + BN * 32 + so, Bl + boff + k0);
            }
        }
        asm volatile("cp.async.commit_group;");
        asm volatile("cp.async.wait_group 2;");
        __syncthreads();

        const uint32_t st = smb + (c % 3) * STAGE;
        uint32_t ah[MT][4], al[MT][4], bh[4][2], bl[4][2];
        #pragma unroll
        for (int mt = 0; mt < MT; mt++) {
            int R = m_w + mt * 16 + rr;
            uint32_t ad = st + R * 32 + ((ccq ^ ((R >> 2) & 1)) << 4);
            ldx4(ah[mt], ad);
            ldx4(al[mt], ad + 4096);
        }
        #pragma unroll
        for (int nt = 0; nt < 4; nt++) {
            int Nr = n_w + nt * 8 + rb;
            uint32_t bd = st + 8192 + Nr * 32 + ((cb ^ ((Nr >> 2) & 1)) << 4);
            ldx2(bh[nt], bd);
            ldx2(bl[nt], bd + BN * 32);
        }
        #pragma unroll
        for (int mt = 0; mt < MT; mt++)
            #pragma unroll
            for (int nt = 0; nt < 4; nt++) {
                mma16816(acc[mt][nt], ah[mt], bh[nt]);
                mma16816(acc[mt][nt], ah[mt], bl[nt]);
                mma16816(acc[mt][nt], al[mt], bh[nt]);
            }
        __syncthreads();
    }

    // ---- epilogue ----
    #pragma unroll
    for (int mt = 0; mt < MT; mt++) {
        int gm0 = m0 + m_w + mt * 16 + (lane >> 2);
        #pragma unroll
        for (int nt = 0; nt < 4; nt++) {
            int gn = n0 + n_w + nt * 8 + (lane & 3) * 2;
            if (gn >= N) continue;
            float bx = 0.f, by = 0.f;
            if (bias) { float2 bv = *(const float2*)(bias + gn); bx = bv.x; by = bv.y; }
            float v0 = acc[mt][nt][0] + bx;
            float v1 = acc[mt][nt][1] + by;
            float v2 = acc[mt][nt][2] + bx;
            float v3 = acc[mt][nt][3] + by;
            if (OUT == 0) {
                if (gm0 < M) {
                    float2 w; w.x = v0; w.y = v1;
                    *(float2*)(C + cbase + (long long)gm0 * ldc + gn) = w;
                }
                if (gm0 + 8 < M) {
                    float2 w; w.x = v2; w.y = v3;
                    *(float2*)(C + cbase + (long long)(gm0 + 8) * ldc + gn) = w;
                }
            } else if (OUT == 3) {
                float2 b2 = *(const float2*)(bias2 + gn);
                float2 b3 = *(const float2*)(bias3 + gn);
                bf16 h0, l0, h1, l1;
                if (gm0 < M) {
                    long long o = cbase + (long long)gm0 * ldc + gn;
                    split_val(v0 + b2.x, h0, l0); split_val(v1 + b2.y, h1, l1);
                    __nv_bfloat162 ph; ph.x = h0; ph.y = h1;
                    __nv_bfloat162 pl; pl.x = l0; pl.y = l1;
                    *(__nv_bfloat162*)(Ch + o) = ph; *(__nv_bfloat162*)(Cl + o) = pl;
                    split_val(v0 + b3.x, h0, l0); split_val(v1 + b3.y, h1, l1);
                    ph.x = h0; ph.y = h1; pl.x = l0; pl.y = l1;
                    *(__nv_bfloat162*)(Dh + o) = ph; *(__nv_bfloat162*)(Dl + o) = pl;
                }
                if (gm0 + 8 < M) {
                    long long o = cbase + (long long)(gm0 + 8) * ldc + gn;
                    split_val(v2 + b2.x, h0, l0); split_val(v3 + b2.y, h1, l1);
                    __nv_bfloat162 ph; ph.x = h0; ph.y = h1;
                    __nv_bfloat162 pl; pl.x = l0; pl.y = l1;
                    *(__nv_bfloat162*)(Ch + o) = ph; *(__nv_bfloat162*)(Cl + o) = pl;
                    split_val(v2 + b3.x, h0, l0); split_val(v3 + b3.y, h1, l1);
                    ph.x = h0; ph.y = h1; pl.x = l0; pl.y = l1;
                    *(__nv_bfloat162*)(Dh + o) = ph; *(__nv_bfloat162*)(Dl + o) = pl;
                }
            } else {
                if (OUT == 2) {
                    v0 = fmaxf(v0, 0.f); v1 = fmaxf(v1, 0.f);
                    v2 = fmaxf(v2, 0.f); v3 = fmaxf(v3, 0.f);
                }
                bf16 h0, l0, h1, l1;
                if (gm0 < M) {
                    long long o = cbase + (long long)gm0 * ldc + gn;
                    split_val(v0, h0, l0); split_val(v1, h1, l1);
                    __nv_bfloat162 ph; ph.x = h0; ph.y = h1;
                    __nv_bfloat162 pl; pl.x = l0; pl.y = l1;
                    *(__nv_bfloat162*)(Ch + o) = ph; *(__nv_bfloat162*)(Cl + o) = pl;
                }
                if (gm0 + 8 < M) {
                    long long o = cbase + (long long)(gm0 + 8) * ldc + gn;
                    split_val(v2, h0, l0); split_val(v3, h1, l1);
                    __nv_bfloat162 ph; ph.x = h0; ph.y = h1;
                    __nv_bfloat162 pl; pl.x = l0; pl.y = l1;
                    *(__nv_bfloat162*)(Ch + o) = ph; *(__nv_bfloat162*)(Cl + o) = pl;
                }
            }
        }
    }
}

// ---------------- reductions ----------------
__device__ __forceinline__ float block_reduce_sum(float v) {
    __shared__ float sm[16];
    __syncthreads();
    #pragma unroll
    for (int o = 16; o > 0; o >>= 1) v += __shfl_xor_sync(0xffffffffu, v, o);
    if ((threadIdx.x & 31) == 0) sm[threadIdx.x >> 5] = v;
    __syncthreads();
    if (threadIdx.x < 32) {
        float x = (threadIdx.x < (blockDim.x >> 5)) ? sm[threadIdx.x] : 0.f;
        #pragma unroll
        for (int o = 8; o > 0; o >>= 1) x += __shfl_xor_sync(0xffffffffu, x, o);
        if (threadIdx.x == 0) sm[0] = x;
    }
    __syncthreads();
    return sm[0];
}
__device__ __forceinline__ float block_reduce_max(float v) {
    __shared__ float sm[16];
    __syncthreads();
    #pragma unroll
    for (int o = 16; o > 0; o >>= 1) v = fmaxf(v, __shfl_xor_sync(0xffffffffu, v, o));
    if ((threadIdx.x & 31) == 0) sm[threadIdx.x >> 5] = v;
    __syncthreads();
    if (threadIdx.x < 32) {
        float x = (threadIdx.x < (blockDim.x >> 5)) ? sm[threadIdx.x] : -3.4e38f;
        #pragma unroll
        for (int o = 8; o > 0; o >>= 1) x = fmaxf(x, __shfl_xor_sync(0xffffffffu, x, o));
        if (threadIdx.x == 0) sm[0] = x;
    }
    __syncthreads();
    return sm[0];
}

// ---------------- small kernels ----------------
__global__ void build_full(const int* __restrict__ tokens,
                           const float* __restrict__ memory,
                           const float* __restrict__ embed,
                           float* __restrict__ x,
                           bf16* __restrict__ xh, bf16* __restrict__ xl,
                           bf16* __restrict__ fullh, bf16* __restrict__ fulll)
{
    long long idx = (long long)blockIdx.x * 256 + threadIdx.x;
    const long long tot = (long long)BB * KLEN * UU;
    if (idx >= tot) return;
    int u = (int)(idx % UU);
    long long t = idx / UU;
    int j = (int)(t % KLEN);
    int b = (int)(t / KLEN);
    float v;
    if (j < MEMLEN) {
        v = memory[((long long)b * MEMLEN + j) * UU + u];
    } else {
        int s = j - MEMLEN;
        int tok = tokens[b * SS + s];
        v = embed[(long long)tok * UU + u] * 32.0f;  // sqrt(1024)
        long long xo = ((long long)b * SS + s) * UU + u;
        x[xo] = v;
        bf16 h, l; split_val(v, h, l);
        xh[xo] = h; xl[xo] = l;
    }
    bf16 h, l; split_val(v, h, l);
    fullh[idx] = h; fulll[idx] = l;
}

__global__ void pos_embed(bf16* __restrict__ relh, bf16* __restrict__ rell)
{
    long long idx = (long long)blockIdx.x * 256 + threadIdx.x;
    if (idx >= (long long)KLEN * UU) return;
    int u = (int)(idx % UU);
    int jj = (int)(idx / UU);
    float pos = (float)(KLEN - 1 - jj);
    int i2 = (u < UU / 2) ? u : (u - UU / 2);
    float expo = ((float)(2 * i2)) / (float)UU;
    float invf = expf(-expo * 9.210340371976184f);  // ln(10000)
    float ang = pos * invf;
    float v = (u < UU / 2) ? sinf(ang) : cosf(ang);
    bf16 h, l; split_val(v, h, l);
    relh[idx] = h; rell[idx] = l;
}

// transpose + split: W[K,N] fp32 -> hi/lo[N,K] bf16 (K,N multiples of 32)
__global__ void split_T(const float* __restrict__ W, bf16* __restrict__ hi,
                        bf16* __restrict__ lo, int K, int N)
{
    __shared__ float t[32][33];
    int n0 = blockIdx.x * 32, k0 = blockIdx.y * 32;
    #pragma unroll
    for (int i = 0; i < 32; i += 8)
        t[threadIdx.y + i][threadIdx.x] =
            W[(long long)(k0 + threadIdx.y + i) * N + n0 + threadIdx.x];
    __syncthreads();
    #pragma unroll
    for (int i = 0; i < 32; i += 8) {
        float v = t[threadIdx.x][threadIdx.y + i];
        long long o = (long long)(n0 + threadIdx.y + i) * K + k0 + threadIdx.x;
        bf16 h, l; split_val(v, h, l);
        hi[o] = h; lo[o] = l;
    }
}

// V^T per head: vt[(b*H+h), d, j] = kv[b, j, U + h*64 + d]
__global__ void transpose_v(const bf16* __restrict__ kvh, const bf16* __restrict__ kvl,
                            bf16* __restrict__ vth, bf16* __restrict__ vtl)
{
    __shared__ bf16 th[32][33], tl[32][33];
    int z = blockIdx.z;
    int b = z / HH, h = z % HH;
    int j0 = blockIdx.x * 32, d0 = blockIdx.y * 32;
    int tx = threadIdx.x, ty = threadIdx.y;
    #pragma unroll
    for (int i = 0; i < 32; i += 8) {
        long long src = ((long long)b * KLEN + j0 + ty + i) * (2 * UU) + UU + h * 64 + d0 + tx;
        th[ty + i][tx] = kvh[src];
        tl[ty + i][tx] = kvl[src];
    }
    __syncthreads();
    #pragma unroll
    for (int i = 0; i < 32; i += 8) {
        long long dst = ((long long)z * DD + d0 + ty + i) * KLEN + j0 + tx;
        vth[dst] = th[tx][ty + i];
        vtl[dst] = tl[tx][ty + i];
    }
}

// mask + rel-shift + softmax; writes P as split bf16 (zero tail)
__global__ __launch_bounds__(256)
void attn_softmax(const float* __restrict__ ac, const float* __restrict__ ar,
                  bf16* __restrict__ ph, bf16* __restrict__ pl)
{
    int i = blockIdx.x;
    long long z = blockIdx.y;
    const float* arow = ac + (z * SS + i) * (long long)KLEN;
    const float* rrow = ar + (z * SS + i) * (long long)KLEN;
    bf16* phr = ph + (z * SS + i) * (long long)KLEN;
    bf16* plr = pl + (z * SS + i) * (long long)KLEN;
    int lim = i + MEMLEN;
    int shift = SS - 1 - i;
    int tid = threadIdx.x;

    float vals[7];
    int cnt = 0;
    float lmax = -3.4e38f;
    for (int j = tid; j <= lim; j += 256) {
        float v = (arow[j] + rrow[j + shift]) * 0.125f;
        vals[cnt++] = v;
        lmax = fmaxf(lmax, v);
    }
    float m = block_reduce_max(lmax);
    float lsum = 0.f;
    for (int t = 0; t < cnt; t++) {
        float e = expf(vals[t] - m);
        vals[t] = e;
        lsum += e;
    }
    float s = block_reduce_sum(lsum);
    float inv = 1.f / s;
    cnt = 0;
    for (int j = tid; j <= lim; j += 256) {
        float p = vals[cnt++] * inv;
        bf16 h, l; split_val(p, h, l);
        phr[j] = h; plr[j] = l;
    }
    bf16 z0 = __float2bfloat16(0.f);
    for (int j = lim + 1 + tid; j < KLEN; j += 256) { phr[j] = z0; plr[j] = z0; }
}

__global__ __launch_bounds__(256)
void add_ln(const float* __restrict__ a, const float* __restrict__ b,
            const float* __restrict__ g, const float* __restrict__ beta,
            float* __restrict__ out, bf16* __restrict__ oh, bf16* __restrict__ ol)
{
    long long row = blockIdx.x;
    const float* pa = a + row * UU;
    const float* pb = b + row * UU;
    int tid = threadIdx.x;
    float vals[4];
    float s = 0.f, ss = 0.f;
    #pragma unroll
    for (int t = 0; t < 4; t++) {
        int idx = tid * 4 + t;
        float v = pa[idx] + pb[idx];
        vals[t] = v;
        s += v;
        ss += v * v;
    }
    s = block_reduce_sum(s);
    ss = block_reduce_sum(ss);
    float mean = s * (1.f / UU);
    float var = fmaxf(ss * (1.f / UU) - mean * mean, 0.f);
    float rstd = rsqrtf(var + 1e-5f);
    #pragma unroll
    for (int t = 0; t < 4; t++) {
        int idx = tid * 4 + t;
        float v = (vals[t] - mean) * rstd * g[idx] + beta[idx];
        out[row * UU + idx] = v;
        bf16 h, l; split_val(v, h, l);
        oh[row * UU + idx] = h; ol[row * UU + idx] = l;
    }
}

// online-softmax over vocab rows, in place
__global__ __launch_bounds__(512)
void softmax_rows(float* __restrict__ x, int N)
{
    __shared__ float smm[16], sms[16];
    long long row = blockIdx.x;
    float* p = x + row * (long long)N;
    int tid = threadIdx.x;
    float m = -3.4e38f, s = 0.f;
    for (int j = tid; j < N; j += 512) {
        float v = p[j];
        if (v > m) { s = s * expf(m - v) + 1.f; m = v; }
        else       { s += expf(v - m); }
    }
    #pragma unroll
    for (int o = 16; o > 0; o >>= 1) {
        float m2 = __shfl_xor_sync(0xffffffffu, m, o);
        float s2 = __shfl_xor_sync(0xffffffffu, s, o);
        float M = fmaxf(m, m2);
        s = s * expf(m - M) + s2 * expf(m2 - M);
        m = M;
    }
    if ((tid & 31) == 0) { smm[tid >> 5] = m; sms[tid >> 5] = s; }
    __syncthreads();
    if (tid < 32) {
        float mm = (tid < 16) ? smm[tid] : -3.4e38f;
        float ssv = (tid < 16) ? sms[tid] : 0.f;
        #pragma unroll
        for (int o = 8; o > 0; o >>= 1) {
            float m2 = __shfl_xor_sync(0xffffffffu, mm, o);
            float s2 = __shfl_xor_sync(0xffffffffu, ssv, o);
            float M = fmaxf(mm, m2);
            ssv = ssv * expf(mm - M) + s2 * expf(m2 - M);
            mm = M;
        }
        if (tid == 0) { smm[0] = mm; sms[0] = ssv; }
    }
    __syncthreads();
    float M = smm[0];
    float inv = 1.f / sms[0];
    for (int j = tid; j < N; j += 512) p[j] = expf(p[j] - M) * inv;
}

// ---------------- host ----------------
extern "C" void kernel_launch(void* const* d_in, const int* in_sizes, int n_in,
                              void* d_out, int out_size)
{
    const int*   tokens  = (const int*)  d_in[0];
    const float* memory  = (const float*)d_in[1];
    const float* embed   = (const float*)d_in[2];
    const float* Wq      = (const float*)d_in[3];
    const float* Wkv     = (const float*)d_in[4];
    const float* Wr      = (const float*)d_in[5];
    const float* Wo      = (const float*)d_in[6];
    const float* bq      = (const float*)d_in[7];
    const float* bkv     = (const float*)d_in[8];
    const float* br      = (const float*)d_in[9];
    const float* bo      = (const float*)d_in[10];
    const float* bias_c  = (const float*)d_in[11];
    const float* bias_r  = (const float*)d_in[12];
    const float* ln1_g   = (const float*)d_in[13];
    const float* ln1_b   = (const float*)d_in[14];
    const float* W1      = (const float*)d_in[15];
    const float* b1      = (const float*)d_in[16];
    const float* W2      = (const float*)d_in[17];
    const float* b2      = (const float*)d_in[18];
    const float* ln2_g   = (const float*)d_in[19];
    const float* ln2_b   = (const float*)d_in[20];
    const float* Wout    = (const float*)d_in[21];
    const float* bout    = (const float*)d_in[22];
    float* out = (float*)d_out;

    float *x, *ac, *ar, *tmp, *h1, *h2;
    cudaGetSymbolAddress((void**)&x,   g_x);
    cudaGetSymbolAddress((void**)&ac,  g_ac);
    cudaGetSymbolAddress((void**)&ar,  g_ar);
    cudaGetSymbolAddress((void**)&tmp, g_tmp);
    cudaGetSymbolAddress((void**)&h1,  g_h1);
    cudaGetSymbolAddress((void**)&h2,  g_h2);

    bf16 *xh,*xl,*fullh,*fulll,*relh,*rell;
    bf16 *qch,*qcl,*qrh,*qrl,*kvh,*kvl,*rh,*rl,*ph,*pl,*vth,*vtl;
    bf16 *ctxh,*ctxl,*h1h,*h1l,*h2h,*h2l,*ffh,*ffl;
    cudaGetSymbolAddress((void**)&xh, g_xh);       cudaGetSymbolAddress((void**)&xl, g_xl);
    cudaGetSymbolAddress((void**)&fullh, g_fullh); cudaGetSymbolAddress((void**)&fulll, g_fulll);
    cudaGetSymbolAddress((void**)&relh, g_relh);   cudaGetSymbolAddress((void**)&rell, g_rell);
    cudaGetSymbolAddress((void**)&qch, g_qch);     cudaGetSymbolAddress((void**)&qcl, g_qcl);
    cudaGetSymbolAddress((void**)&qrh, g_qrh);     cudaGetSymbolAddress((void**)&qrl, g_qrl);
    cudaGetSymbolAddress((void**)&kvh, g_kvh);     cudaGetSymbolAddress((void**)&kvl, g_kvl);
    cudaGetSymbolAddress((void**)&rh, g_rh);       cudaGetSymbolAddress((void**)&rl, g_rl);
    cudaGetSymbolAddress((void**)&ph, g_ph);       cudaGetSymbolAddress((void**)&pl, g_pl);
    cudaGetSymbolAddress((void**)&vth, g_vth);     cudaGetSymbolAddress((void**)&vtl, g_vtl);
    cudaGetSymbolAddress((void**)&ctxh, g_ctxh);   cudaGetSymbolAddress((void**)&ctxl, g_ctxl);
    cudaGetSymbolAddress((void**)&h1h, g_h1h);     cudaGetSymbolAddress((void**)&h1l, g_h1l);
    cudaGetSymbolAddress((void**)&h2h, g_h2h);     cudaGetSymbolAddress((void**)&h2l, g_h2l);
    cudaGetSymbolAddress((void**)&ffh, g_ffh);     cudaGetSymbolAddress((void**)&ffl, g_ffl);

    bf16 *WqTh,*WqTl,*WkvTh,*WkvTl,*WrTh,*WrTl,*WoTh,*WoTl,*W1Th,*W1Tl,*W2Th,*W2Tl,*WoutTh,*WoutTl;
    cudaGetSymbolAddress((void**)&WqTh, g_WqTh);   cudaGetSymbolAddress((void**)&WqTl, g_WqTl);
    cudaGetSymbolAddress((void**)&WkvTh, g_WkvTh); cudaGetSymbolAddress((void**)&WkvTl, g_WkvTl);
    cudaGetSymbolAddress((void**)&WrTh, g_WrTh);   cudaGetSymbolAddress((void**)&WrTl, g_WrTl);
    cudaGetSymbolAddress((void**)&WoTh, g_WoTh);   cudaGetSymbolAddress((void**)&WoTl, g_WoTl);
    cudaGetSymbolAddress((void**)&W1Th, g_W1Th);   cudaGetSymbolAddress((void**)&W1Tl, g_W1Tl);
    cudaGetSymbolAddress((void**)&W2Th, g_W2Th);   cudaGetSymbolAddress((void**)&W2Tl, g_W2Tl);
    cudaGetSymbolAddress((void**)&WoutTh, g_WoutTh); cudaGetSymbolAddress((void**)&WoutTl, g_WoutTl);

    const int M_TOK = BB * SS;      // 2048
    const int M_FULL = BB * KLEN;   // 3200
    dim3 tb(32, 8);

    // launch order arranged so ncu (-s 5 -c 1) captures the kv hgemm (6th launch)
    // 1) embedding + concat + splits
    {
        long long tot = (long long)BB * KLEN * UU;
        build_full<<<(unsigned)((tot + 255) / 256), 256>>>(tokens, memory, embed,
                                                           x, xh, xl, fullh, fulll);
    }
    // 2) positional embedding
    {
        long long tot = (long long)KLEN * UU;
        pos_embed<<<(unsigned)((tot + 255) / 256), 256>>>(relh, rell);
    }
    // 3,4) first two weight splits
    split_T<<<dim3(UU/32,  UU/32), tb>>>(Wq,  WqTh,  WqTl,  UU, UU);
    split_T<<<dim3(2*UU/32,UU/32), tb>>>(Wkv, WkvTh, WkvTl, UU, 2*UU);
    // 5) q projection fused with (q+u)/(q+v) splits (OUT=3)
    hgemm<128,3><<<dim3(M_TOK/128, UU/128, 1), 256>>>(
        xh, xl, WqTh, WqTl, nullptr, qch, qcl, qrh, qrl, bq, bias_c, bias_r,
        M_TOK, UU, UU, UU, UU, UU, 1, 0,0,0,0,0,0);
    // 6) kv projection  <-- ncu capture target
    hgemm<128,1><<<dim3((M_FULL+127)/128, 2*UU/128, 1), 256>>>(
        fullh, fulll, WkvTh, WkvTl, nullptr, kvh, kvl, nullptr, nullptr, bkv, nullptr, nullptr,
        M_FULL, 2*UU, UU, UU, UU, 2*UU, 1, 0,0,0,0,0,0);
    // remaining weight splits
    split_T<<<dim3(UU/32,  UU/32),  tb>>>(Wr,   WrTh,   WrTl,   UU,  UU);
    split_T<<<dim3(UU/32,  UU/32),  tb>>>(Wo,   WoTh,   WoTl,   UU,  UU);
    split_T<<<dim3(FFD/32, UU/32),  tb>>>(W1,   W1Th,   W1Tl,   UU,  FFD);
    split_T<<<dim3(UU/32,  FFD/32), tb>>>(W2,   W2Th,   W2Tl,   FFD, UU);
    split_T<<<dim3(NT/32,  UU/32),  tb>>>(Wout, WoutTh, WoutTl, UU,  NT);
    // r projection
    hgemm<128,1><<<dim3((KLEN+127)/128, UU/128, 1), 256>>>(
        relh, rell, WrTh, WrTl, nullptr, rh, rl, nullptr, nullptr, br, nullptr, nullptr,
        KLEN, UU, UU, UU, UU, UU, 1, 0,0,0,0,0,0);
    // scores (batched over b,h)
    {
        dim3 grid(SS / 128, (KLEN + 127) / 128, BB * HH);
        hgemm<128,0><<<grid, 256>>>(qch, qcl, kvh, kvl, ac, nullptr, nullptr, nullptr, nullptr,
            nullptr, nullptr, nullptr,
            SS, KLEN, DD, UU, 2*UU, KLEN, HH,
            (long long)SS*UU, 64,
            (long long)KLEN*2*UU, 64,
            (long long)HH*SS*KLEN, (long long)SS*KLEN);
        hgemm<128,0><<<grid, 256>>>(qrh, qrl, rh, rl, ar, nullptr, nullptr, nullptr, nullptr,
            nullptr, nullptr, nullptr,
            SS, KLEN, DD, UU, UU, KLEN, HH,
            (long long)SS*UU, 64,
            0, 64,
            (long long)HH*SS*KLEN, (long long)SS*KLEN);
    }
    // fused rel-shift + mask + softmax -> split P
    {
        dim3 grid(SS, BB * HH);
        attn_softmax<<<grid, 256>>>(ac, ar, ph, pl);
    }
    // V^T per head
    {
        dim3 grid(KLEN / 32, DD / 32, BB * HH);
        transpose_v<<<grid, tb>>>(kvh, kvl, vth, vtl);
    }
    // ctx = P @ V^T
    {
        dim3 grid(SS / 128, 1, BB * HH);
        hgemm<64,1><<<grid, 256>>>(ph, pl, vth, vtl, nullptr, ctxh, ctxl, nullptr, nullptr,
            nullptr, nullptr, nullptr,
            SS, DD, KLEN, KLEN, KLEN, UU, HH,
            (long long)HH*SS*KLEN, (long long)SS*KLEN,
            (long long)HH*DD*KLEN, (long long)DD*KLEN,
            (long long)SS*UU, 64);
    }
    // attention out projection + LN1
    hgemm<128,0><<<dim3(M_TOK/128, UU/128, 1), 256>>>(
        ctxh, ctxl, WoTh, WoTl, tmp, nullptr, nullptr, nullptr, nullptr, bo, nullptr, nullptr,
        M_TOK, UU, UU, UU, UU, UU, 1, 0,0,0,0,0,0);
    add_ln<<<M_TOK, 256>>>(x, tmp, ln1_g, ln1_b, h1, h1h, h1l);
    // FF
    hgemm<128,2><<<dim3(M_TOK/128, FFD/128, 1), 256>>>(
        h1h, h1l, W1Th, W1Tl, nullptr, ffh, ffl, nullptr, nullptr, b1, nullptr, nullptr,
        M_TOK, FFD, UU, UU, UU, FFD, 1, 0,0,0,0,0,0);
    hgemm<128,0><<<dim3(M_TOK/128, UU/128, 1), 256>>>(
        ffh, ffl, W2Th, W2Tl, tmp, nullptr, nullptr, nullptr, nullptr, b2, nullptr, nullptr,
        M_TOK, UU, FFD, FFD, FFD, UU, 1, 0,0,0,0,0,0);
    add_ln<<<M_TOK, 256>>>(h1, tmp, ln2_g, ln2_b, h2, h2h, h2l);
    // logits + softmax
    hgemm<128,0><<<dim3(M_TOK/128, NT/128, 1), 256>>>(
        h2h, h2l, WoutTh, WoutTl, out, nullptr, nullptr, nullptr, nullptr, bout, nullptr, nullptr,
        M_TOK, NT, UU, UU, UU, NT, 1, 0,0,0,0,0,0);
    softmax_rows<<<M_TOK, 512>>>(out, NT);
}

// round 7
// speedup vs baseline: 1.1762x; 1.1762x over previous
#include <cuda_runtime.h>
#include <cuda_bf16.h>
#include <cuda_fp16.h>
#include <math.h>
#include <stdint.h>

// ---------------- problem constants ----------------
#define BB 2
#define SS 1024
#define UU 1024
#define HH 16
#define DD 64
#define NT 32000
#define MEMLEN 576
#define FFD 4096
#define KLEN 1600   // MEM + S
#define VOCAB 1024

typedef __nv_bfloat16 bf16;

// ---------------- scratch (device globals; no allocation allowed) ----------------
__device__ float g_ac  [(size_t)BB*HH*SS*KLEN];
__device__ float g_ar  [(size_t)BB*HH*SS*KLEN];
__device__ float g_x   [(size_t)BB*SS*UU];
__device__ float g_tmp [(size_t)BB*SS*UU];
__device__ float g_h1  [(size_t)BB*SS*UU];

__device__ bf16 g_xh   [(size_t)BB*SS*UU],   g_xl   [(size_t)BB*SS*UU];
__device__ bf16 g_fullh[(size_t)BB*KLEN*UU], g_fulll[(size_t)BB*KLEN*UU];
__device__ bf16 g_relh [(size_t)KLEN*UU],    g_rell [(size_t)KLEN*UU];
__device__ bf16 g_qch  [(size_t)BB*SS*UU],   g_qcl  [(size_t)BB*SS*UU];
__device__ bf16 g_qrh  [(size_t)BB*SS*UU],   g_qrl  [(size_t)BB*SS*UU];
__device__ bf16 g_kvh  [(size_t)BB*KLEN*2*UU], g_kvl [(size_t)BB*KLEN*2*UU];
__device__ bf16 g_rh   [(size_t)KLEN*UU],    g_rl   [(size_t)KLEN*UU];
__device__ bf16 g_ph   [(size_t)BB*HH*SS*KLEN], g_pl [(size_t)BB*HH*SS*KLEN];
__device__ bf16 g_vth  [(size_t)BB*HH*DD*KLEN], g_vtl[(size_t)BB*HH*DD*KLEN];
__device__ bf16 g_ctxh [(size_t)BB*SS*UU],   g_ctxl [(size_t)BB*SS*UU];
__device__ bf16 g_h1h  [(size_t)BB*SS*UU],   g_h1l  [(size_t)BB*SS*UU];
__device__ bf16 g_ffh  [(size_t)BB*SS*FFD],  g_ffl  [(size_t)BB*SS*FFD];
// fp16 buffers for the 2-pass logits path
__device__ __half g_h2hh[(size_t)BB*SS*UU],  g_h2lh [(size_t)BB*SS*UU];
__device__ __half g_WoutH[(size_t)NT*UU];
// transposed weights [N,K] bf16 hi/lo
__device__ bf16 g_WqTh [(size_t)UU*UU],    g_WqTl [(size_t)UU*UU];
__device__ bf16 g_WkvTh[(size_t)2*UU*UU],  g_WkvTl[(size_t)2*UU*UU];
__device__ bf16 g_WrTh [(size_t)UU*UU],    g_WrTl [(size_t)UU*UU];
__device__ bf16 g_WoTh [(size_t)UU*UU],    g_WoTl [(size_t)UU*UU];
__device__ bf16 g_W1Th [(size_t)FFD*UU],   g_W1Tl [(size_t)FFD*UU];
__device__ bf16 g_W2Th [(size_t)UU*FFD],   g_W2Tl [(size_t)UU*FFD];

// ---------------- helpers ----------------
__device__ __forceinline__ uint32_t smem_u32(const void* p) {
    uint32_t a;
    asm("{ .reg .u64 t; cvta.to.shared.u64 t, %1; cvt.u32.u64 %0, t; }" : "=r"(a) : "l"(p));
    return a;
}
__device__ __forceinline__ void split_val(float v, bf16& h, bf16& l) {
    h = __float2bfloat16(v);
    l = __float2bfloat16(v - __bfloat162float(h));
}
__device__ __forceinline__ void split_to(float v, bf16& h, bf16& l) {
    h = __float2bfloat16(v);
    l = __float2bfloat16(v - __bfloat162float(h));
}
__device__ __forceinline__ void split_to(float v, __half& h, __half& l) {
    h = __float2half(v);
    l = __float2half(v - __half2float(h));
}
__device__ __forceinline__ void cp16(uint32_t dst, const void* src) {
    asm volatile("cp.async.cg.shared.global [%0], [%1], 16;" :: "r"(dst), "l"(src));
}
__device__ __forceinline__ void ldx4(uint32_t* r, uint32_t addr) {
    asm volatile("ldmatrix.sync.aligned.m8n8.x4.shared.b16 {%0,%1,%2,%3}, [%4];"
                 : "=r"(r[0]), "=r"(r[1]), "=r"(r[2]), "=r"(r[3]) : "r"(addr));
}
__device__ __forceinline__ void ldx2(uint32_t* r, uint32_t addr) {
    asm volatile("ldmatrix.sync.aligned.m8n8.x2.shared.b16 {%0,%1}, [%2];"
                 : "=r"(r[0]), "=r"(r[1]) : "r"(addr));
}
__device__ __forceinline__ void mma_bf(float* c, const uint32_t* a, const uint32_t* b) {
    asm volatile("mma.sync.aligned.m16n8k16.row.col.f32.bf16.bf16.f32 "
                 "{%0,%1,%2,%3}, {%4,%5,%6,%7}, {%8,%9}, {%0,%1,%2,%3};"
                 : "+f"(c[0]), "+f"(c[1]), "+f"(c[2]), "+f"(c[3])
                 : "r"(a[0]), "r"(a[1]), "r"(a[2]), "r"(a[3]), "r"(b[0]), "r"(b[1]));
}
__device__ __forceinline__ void mma_fp(float* c, const uint32_t* a, const uint32_t* b) {
    asm volatile("mma.sync.aligned.m16n8k16.row.col.f32.f16.f16.f32 "
                 "{%0,%1,%2,%3}, {%4,%5,%6,%7}, {%8,%9}, {%0,%1,%2,%3};"
                 : "+f"(c[0]), "+f"(c[1]), "+f"(c[2]), "+f"(c[3])
                 : "r"(a[0]), "r"(a[1]), "r"(a[2]), "r"(a[3]), "r"(b[0]), "r"(b[1]));
}

// ---------------- generalized HMMA split GEMM ----------------
// PASS=3 (bf16): C = (Ah+Al) @ (Bh+Bl)^T via hh + hl + lh.
// PASS=2 (fp16): C = (Ah+Al) @ Bh^T (B single fp16, Bl unused) via hh + lh.
// GRID: blockIdx.x = M-tile, blockIdx.y = N-tile, blockIdx.z = batch.
// OUT: 0 = fp32 C (+bias); 1 = split bf16 Ch/Cl; 2 = relu + split;
//      3 = dual-bias split: Ch/Cl = split(v+bias2), Dh/Dl = split(v+bias3).
template<int BN, int OUT, int PASS>
__global__ __launch_bounds__(256)
void hgemm(const bf16* __restrict__ Ah, const bf16* __restrict__ Al,
           const bf16* __restrict__ Bh, const bf16* __restrict__ Bl,
           float* __restrict__ C, bf16* __restrict__ Ch, bf16* __restrict__ Cl,
           bf16* __restrict__ Dh, bf16* __restrict__ Dl,
           const float* __restrict__ bias,
           const float* __restrict__ bias2, const float* __restrict__ bias3,
           int M, int N, int K, int lda, int ldb, int ldc, int Z2,
           long long sA1, long long sA2, long long sB1, long long sB2,
           long long sC1, long long sC2)
{
    constexpr int BSTR = BN * 32;
    constexpr int STAGE = 8192 + (PASS == 3 ? 2 : 1) * BSTR;
    constexpr int MT = (BN == 128) ? 4 : 2;
    __shared__ __align__(128) char sm[3 * STAGE];
    const uint32_t smb = smem_u32(sm);
    const int tid = threadIdx.x, wid = tid >> 5, lane = tid & 31;
    const int m0 = blockIdx.x * 128, n0 = blockIdx.y * BN;
    const int m_w = (BN == 128) ? (wid & 1) * 64 : (wid & 3) * 32;
    const int n_w = (BN == 128) ? (wid >> 1) * 32 : (wid >> 2) * 32;

    const int z = blockIdx.z;
    const int z1 = z / Z2, z2 = z - z1 * Z2;
    Ah += z1 * sA1 + z2 * sA2;  Al += z1 * sA1 + z2 * sA2;
    Bh += z1 * sB1 + z2 * sB2;
    if (PASS == 3) Bl += z1 * sB1 + z2 * sB2;
    const long long cbase = z1 * sC1 + z2 * sC2;

    const int lr = tid >> 1, lc = tid & 1;
    const uint32_t so = (uint32_t)(lr * 32 + ((lc ^ ((lr >> 2) & 1)) << 4));
    const int ga = min(m0 + lr, M - 1);
    const long long aoff = (long long)ga * lda + lc * 8;
    const bool bdo = (BN == 128) || (tid < 128);
    const int gb = min(n0 + lr, N - 1);
    const long long boff = (long long)gb * ldb + lc * 8;

    float acc[MT][4][4];
    #pragma unroll
    for (int i = 0; i < MT; i++)
        #pragma unroll
        for (int j = 0; j < 4; j++)
            #pragma unroll
            for (int k = 0; k < 4; k++) acc[i][j][k] = 0.f;

    const int NC = K / 16;

    #pragma unroll
    for (int pc = 0; pc < 2; pc++) {
        const uint32_t st = smb + pc * STAGE;
        cp16(st + so,        Ah + aoff + pc * 16);
        cp16(st + 4096 + so, Al + aoff + pc * 16);
        if (bdo) {
            cp16(st + 8192 + so, Bh + boff + pc * 16);
            if (PASS == 3) cp16(st + 8192 + BSTR + so, Bl + boff + pc * 16);
        }
        asm volatile("cp.async.commit_group;");
    }

    const int rr = lane & 15, ccq = lane >> 4;
    const int rb = lane & 7,  cb = (lane >> 3) & 1;

    for (int c = 0; c < NC; c++) {
        if (c + 2 < NC) {
            const uint32_t st = smb + ((c + 2) % 3) * STAGE;
            const long long k0 = (long long)(c + 2) * 16;
            cp16(st + so,        Ah + aoff + k0);
            cp16(st + 4096 + so, Al + aoff + k0);
            if (bdo) {
                cp16(st + 8192 + so, Bh + boff + k0);
                if (PASS == 3) cp16(st + 8192 + BSTR + so, Bl + boff + k0);
            }
        }
        asm volatile("cp.async.commit_group;");
        asm volatile("cp.async.wait_group 2;");
        __syncthreads();

        const uint32_t st = smb + (c % 3) * STAGE;
        uint32_t ah[MT][4], al[MT][4], bh[4][2], bl[4][2];
        #pragma unroll
        for (int mt = 0; mt < MT; mt++) {
            int R = m_w + mt * 16 + rr;
            uint32_t ad = st + R * 32 + ((ccq ^ ((R >> 2) & 1)) << 4);
            ldx4(ah[mt], ad);
            ldx4(al[mt], ad + 4096);
        }
        #pragma unroll
        for (int nt = 0; nt < 4; nt++) {
            int Nr = n_w + nt * 8 + rb;
            uint32_t bd = st + 8192 + Nr * 32 + ((cb ^ ((Nr >> 2) & 1)) << 4);
            ldx2(bh[nt], bd);
            if (PASS == 3) ldx2(bl[nt], bd + BSTR);
        }
        #pragma unroll
        for (int mt = 0; mt < MT; mt++)
            #pragma unroll
            for (int nt = 0; nt < 4; nt++) {
                if (PASS == 3) {
                    mma_bf(acc[mt][nt], ah[mt], bh[nt]);
                    mma_bf(acc[mt][nt], ah[mt], bl[nt]);
                    mma_bf(acc[mt][nt], al[mt], bh[nt]);
                } else {
                    mma_fp(acc[mt][nt], ah[mt], bh[nt]);
                    mma_fp(acc[mt][nt], al[mt], bh[nt]);
                }
            }
        __syncthreads();
    }

    // ---- epilogue ----
    #pragma unroll
    for (int mt = 0; mt < MT; mt++) {
        int gm0 = m0 + m_w + mt * 16 + (lane >> 2);
        #pragma unroll
        for (int nt = 0; nt < 4; nt++) {
            int gn = n0 + n_w + nt * 8 + (lane & 3) * 2;
            if (gn >= N) continue;
            float bx = 0.f, by = 0.f;
            if (bias) { float2 bv = *(const float2*)(bias + gn); bx = bv.x; by = bv.y; }
            float v0 = acc[mt][nt][0] + bx;
            float v1 = acc[mt][nt][1] + by;
            float v2 = acc[mt][nt][2] + bx;
            float v3 = acc[mt][nt][3] + by;
            if (OUT == 0) {
                if (gm0 < M) {
                    float2 w; w.x = v0; w.y = v1;
                    *(float2*)(C + cbase + (long long)gm0 * ldc + gn) = w;
                }
                if (gm0 + 8 < M) {
                    float2 w; w.x = v2; w.y = v3;
                    *(float2*)(C + cbase + (long long)(gm0 + 8) * ldc + gn) = w;
                }
            } else if (OUT == 3) {
                float2 b2 = *(const float2*)(bias2 + gn);
                float2 b3 = *(const float2*)(bias3 + gn);
                bf16 h0, l0, h1, l1;
                if (gm0 < M) {
                    long long o = cbase + (long long)gm0 * ldc + gn;
                    split_val(v0 + b2.x, h0, l0); split_val(v1 + b2.y, h1, l1);
                    __nv_bfloat162 ph; ph.x = h0; ph.y = h1;
                    __nv_bfloat162 pl; pl.x = l0; pl.y = l1;
                    *(__nv_bfloat162*)(Ch + o) = ph; *(__nv_bfloat162*)(Cl + o) = pl;
                    split_val(v0 + b3.x, h0, l0); split_val(v1 + b3.y, h1, l1);
                    ph.x = h0; ph.y = h1; pl.x = l0; pl.y = l1;
                    *(__nv_bfloat162*)(Dh + o) = ph; *(__nv_bfloat162*)(Dl + o) = pl;
                }
                if (gm0 + 8 < M) {
                    long long o = cbase + (long long)(gm0 + 8) * ldc + gn;
                    split_val(v2 + b2.x, h0, l0); split_val(v3 + b2.y, h1, l1);
                    __nv_bfloat162 ph; ph.x = h0; ph.y = h1;
                    __nv_bfloat162 pl; pl.x = l0; pl.y = l1;
                    *(__nv_bfloat162*)(Ch + o) = ph; *(__nv_bfloat162*)(Cl + o) = pl;
                    split_val(v2 + b3.x, h0, l0); split_val(v3 + b3.y, h1, l1);
                    ph.x = h0; ph.y = h1; pl.x = l0; pl.y = l1;
                    *(__nv_bfloat162*)(Dh + o) = ph; *(__nv_bfloat162*)(Dl + o) = pl;
                }
            } else {
                if (OUT == 2) {
                    v0 = fmaxf(v0, 0.f); v1 = fmaxf(v1, 0.f);
                    v2 = fmaxf(v2, 0.f); v3 = fmaxf(v3, 0.f);
                }
                bf16 h0, l0, h1, l1;
                if (gm0 < M) {
                    long long o = cbase + (long long)gm0 * ldc + gn;
                    split_val(v0, h0, l0); split_val(v1, h1, l1);
                    __nv_bfloat162 ph; ph.x = h0; ph.y = h1;
                    __nv_bfloat162 pl; pl.x = l0; pl.y = l1;
                    *(__nv_bfloat162*)(Ch + o) = ph; *(__nv_bfloat162*)(Cl + o) = pl;
                }
                if (gm0 + 8 < M) {
                    long long o = cbase + (long long)(gm0 + 8) * ldc + gn;
                    split_val(v2, h0, l0); split_val(v3, h1, l1);
                    __nv_bfloat162 ph; ph.x = h0; ph.y = h1;
                    __nv_bfloat162 pl; pl.x = l0; pl.y = l1;
                    *(__nv_bfloat162*)(Ch + o) = ph; *(__nv_bfloat162*)(Cl + o) = pl;
                }
            }
        }
    }
}

// ---------------- reductions ----------------
__device__ __forceinline__ float block_reduce_sum(float v) {
    __shared__ float sm[16];
    __syncthreads();
    #pragma unroll
    for (int o = 16; o > 0; o >>= 1) v += __shfl_xor_sync(0xffffffffu, v, o);
    if ((threadIdx.x & 31) == 0) sm[threadIdx.x >> 5] = v;
    __syncthreads();
    if (threadIdx.x < 32) {
        float x = (threadIdx.x < (blockDim.x >> 5)) ? sm[threadIdx.x] : 0.f;
        #pragma unroll
        for (int o = 8; o > 0; o >>= 1) x += __shfl_xor_sync(0xffffffffu, x, o);
        if (threadIdx.x == 0) sm[0] = x;
    }
    __syncthreads();
    return sm[0];
}
__device__ __forceinline__ float block_reduce_max(float v) {
    __shared__ float sm[16];
    __syncthreads();
    #pragma unroll
    for (int o = 16; o > 0; o >>= 1) v = fmaxf(v, __shfl_xor_sync(0xffffffffu, v, o));
    if ((threadIdx.x & 31) == 0) sm[threadIdx.x >> 5] = v;
    __syncthreads();
    if (threadIdx.x < 32) {
        float x = (threadIdx.x < (blockDim.x >> 5)) ? sm[threadIdx.x] : -3.4e38f;
        #pragma unroll
        for (int o = 8; o > 0; o >>= 1) x = fmaxf(x, __shfl_xor_sync(0xffffffffu, x, o));
        if (threadIdx.x == 0) sm[0] = x;
    }
    __syncthreads();
    return sm[0];
}

// ---------------- small kernels ----------------
__global__ void build_full(const int* __restrict__ tokens,
                           const float* __restrict__ memory,
                           const float* __restrict__ embed,
                           float* __restrict__ x,
                           bf16* __restrict__ xh, bf16* __restrict__ xl,
                           bf16* __restrict__ fullh, bf16* __restrict__ fulll)
{
    long long idx = (long long)blockIdx.x * 256 + threadIdx.x;
    const long long tot = (long long)BB * KLEN * UU;
    if (idx >= tot) return;
    int u = (int)(idx % UU);
    long long t = idx / UU;
    int j = (int)(t % KLEN);
    int b = (int)(t / KLEN);
    float v;
    if (j < MEMLEN) {
        v = memory[((long long)b * MEMLEN + j) * UU + u];
    } else {
        int s = j - MEMLEN;
        int tok = tokens[b * SS + s];
        v = embed[(long long)tok * UU + u] * 32.0f;  // sqrt(1024)
        long long xo = ((long long)b * SS + s) * UU + u;
        x[xo] = v;
        bf16 h, l; split_val(v, h, l);
        xh[xo] = h; xl[xo] = l;
    }
    bf16 h, l; split_val(v, h, l);
    fullh[idx] = h; fulll[idx] = l;
}

__global__ void pos_embed(bf16* __restrict__ relh, bf16* __restrict__ rell)
{
    long long idx = (long long)blockIdx.x * 256 + threadIdx.x;
    if (idx >= (long long)KLEN * UU) return;
    int u = (int)(idx % UU);
    int jj = (int)(idx / UU);
    float pos = (float)(KLEN - 1 - jj);
    int i2 = (u < UU / 2) ? u : (u - UU / 2);
    float expo = ((float)(2 * i2)) / (float)UU;
    float invf = expf(-expo * 9.210340371976184f);  // ln(10000)
    float ang = pos * invf;
    float v = (u < UU / 2) ? sinf(ang) : cosf(ang);
    bf16 h, l; split_val(v, h, l);
    relh[idx] = h; rell[idx] = l;
}

// transpose + split: W[K,N] fp32 -> hi/lo[N,K] bf16
__global__ void split_T(const float* __restrict__ W, bf16* __restrict__ hi,
                        bf16* __restrict__ lo, int K, int N)
{
    __shared__ float t[32][33];
    int n0 = blockIdx.x * 32, k0 = blockIdx.y * 32;
    #pragma unroll
    for (int i = 0; i < 32; i += 8)
        t[threadIdx.y + i][threadIdx.x] =
            W[(long long)(k0 + threadIdx.y + i) * N + n0 + threadIdx.x];
    __syncthreads();
    #pragma unroll
    for (int i = 0; i < 32; i += 8) {
        float v = t[threadIdx.x][threadIdx.y + i];
        long long o = (long long)(n0 + threadIdx.y + i) * K + k0 + threadIdx.x;
        bf16 h, l; split_val(v, h, l);
        hi[o] = h; lo[o] = l;
    }
}

// transpose: W[K,N] fp32 -> single fp16 [N,K]
__global__ void split_T_h(const float* __restrict__ W, __half* __restrict__ hi,
                          int K, int N)
{
    __shared__ float t[32][33];
    int n0 = blockIdx.x * 32, k0 = blockIdx.y * 32;
    #pragma unroll
    for (int i = 0; i < 32; i += 8)
        t[threadIdx.y + i][threadIdx.x] =
            W[(long long)(k0 + threadIdx.y + i) * N + n0 + threadIdx.x];
    __syncthreads();
    #pragma unroll
    for (int i = 0; i < 32; i += 8) {
        float v = t[threadIdx.x][threadIdx.y + i];
        long long o = (long long)(n0 + threadIdx.y + i) * K + k0 + threadIdx.x;
        hi[o] = __float2half(v);
    }
}

// V^T per head: vt[(b*H+h), d, j] = kv[b, j, U + h*64 + d]
__global__ void transpose_v(const bf16* __restrict__ kvh, const bf16* __restrict__ kvl,
                            bf16* __restrict__ vth, bf16* __restrict__ vtl)
{
    __shared__ bf16 th[32][33], tl[32][33];
    int z = blockIdx.z;
    int b = z / HH, h = z % HH;
    int j0 = blockIdx.x * 32, d0 = blockIdx.y * 32;
    int tx = threadIdx.x, ty = threadIdx.y;
    #pragma unroll
    for (int i = 0; i < 32; i += 8) {
        long long src = ((long long)b * KLEN + j0 + ty + i) * (2 * UU) + UU + h * 64 + d0 + tx;
        th[ty + i][tx] = kvh[src];
        tl[ty + i][tx] = kvl[src];
    }
    __syncthreads();
    #pragma unroll
    for (int i = 0; i < 32; i += 8) {
        long long dst = ((long long)z * DD + d0 + ty + i) * KLEN + j0 + tx;
        vth[dst] = th[tx][ty + i];
        vtl[dst] = tl[tx][ty + i];
    }
}

// mask + rel-shift + softmax; writes P as split bf16 (zero tail)
__global__ __launch_bounds__(256)
void attn_softmax(const float* __restrict__ ac, const float* __restrict__ ar,
                  bf16* __restrict__ ph, bf16* __restrict__ pl)
{
    int i = blockIdx.x;
    long long z = blockIdx.y;
    const float* arow = ac + (z * SS + i) * (long long)KLEN;
    const float* rrow = ar + (z * SS + i) * (long long)KLEN;
    bf16* phr = ph + (z * SS + i) * (long long)KLEN;
    bf16* plr = pl + (z * SS + i) * (long long)KLEN;
    int lim = i + MEMLEN;
    int shift = SS - 1 - i;
    int tid = threadIdx.x;

    float vals[7];
    int cnt = 0;
    float lmax = -3.4e38f;
    for (int j = tid; j <= lim; j += 256) {
        float v = (arow[j] + rrow[j + shift]) * 0.125f;
        vals[cnt++] = v;
        lmax = fmaxf(lmax, v);
    }
    float m = block_reduce_max(lmax);
    float lsum = 0.f;
    for (int t = 0; t < cnt; t++) {
        float e = expf(vals[t] - m);
        vals[t] = e;
        lsum += e;
    }
    float s = block_reduce_sum(lsum);
    float inv = 1.f / s;
    cnt = 0;
    for (int j = tid; j <= lim; j += 256) {
        float p = vals[cnt++] * inv;
        bf16 h, l; split_val(p, h, l);
        phr[j] = h; plr[j] = l;
    }
    bf16 z0 = __float2bfloat16(0.f);
    for (int j = lim + 1 + tid; j < KLEN; j += 256) { phr[j] = z0; plr[j] = z0; }
}

// add + LayerNorm; emits fp32 (optional) plus split pair of type T
template<typename T>
__global__ __launch_bounds__(256)
void add_ln(const float* __restrict__ a, const float* __restrict__ b,
            const float* __restrict__ g, const float* __restrict__ beta,
            float* __restrict__ out, T* __restrict__ oh, T* __restrict__ ol)
{
    long long row = blockIdx.x;
    const float* pa = a + row * UU;
    const float* pb = b + row * UU;
    int tid = threadIdx.x;
    float vals[4];
    float s = 0.f, ss = 0.f;
    #pragma unroll
    for (int t = 0; t < 4; t++) {
        int idx = tid * 4 + t;
        float v = pa[idx] + pb[idx];
        vals[t] = v;
        s += v;
        ss += v * v;
    }
    s = block_reduce_sum(s);
    ss = block_reduce_sum(ss);
    float mean = s * (1.f / UU);
    float var = fmaxf(ss * (1.f / UU) - mean * mean, 0.f);
    float rstd = rsqrtf(var + 1e-5f);
    #pragma unroll
    for (int t = 0; t < 4; t++) {
        int idx = tid * 4 + t;
        float v = (vals[t] - mean) * rstd * g[idx] + beta[idx];
        if (out) out[row * UU + idx] = v;
        T h, l; split_to(v, h, l);
        oh[row * UU + idx] = h; ol[row * UU + idx] = l;
    }
}

// online-softmax over vocab rows, in place
__global__ __launch_bounds__(512)
void softmax_rows(float* __restrict__ x, int N)
{
    __shared__ float smm[16], sms[16];
    long long row = blockIdx.x;
    float* p = x + row * (long long)N;
    int tid = threadIdx.x;
    float m = -3.4e38f, s = 0.f;
    for (int j = tid; j < N; j += 512) {
        float v = p[j];
        if (v > m) { s = s * expf(m - v) + 1.f; m = v; }
        else       { s += expf(v - m); }
    }
    #pragma unroll
    for (int o = 16; o > 0; o >>= 1) {
        float m2 = __shfl_xor_sync(0xffffffffu, m, o);
        float s2 = __shfl_xor_sync(0xffffffffu, s, o);
        float M = fmaxf(m, m2);
        s = s * expf(m - M) + s2 * expf(m2 - M);
        m = M;
    }
    if ((tid & 31) == 0) { smm[tid >> 5] = m; sms[tid >> 5] = s; }
    __syncthreads();
    if (tid < 32) {
        float mm = (tid < 16) ? smm[tid] : -3.4e38f;
        float ssv = (tid < 16) ? sms[tid] : 0.f;
        #pragma unroll
        for (int o = 8; o > 0; o >>= 1) {
            float m2 = __shfl_xor_sync(0xffffffffu, mm, o);
            float s2 = __shfl_xor_sync(0xffffffffu, ssv, o);
            float M = fmaxf(mm, m2);
            ssv = ssv * expf(mm - M) + s2 * expf(m2 - M);
            mm = M;
        }
        if (tid == 0) { smm[0] = mm; sms[0] = ssv; }
    }
    __syncthreads();
    float M = smm[0];
    float inv = 1.f / sms[0];
    for (int j = tid; j < N; j += 512) p[j] = expf(p[j] - M) * inv;
}

// ---------------- host ----------------
extern "C" void kernel_launch(void* const* d_in, const int* in_sizes, int n_in,
                              void* d_out, int out_size)
{
    const int*   tokens  = (const int*)  d_in[0];
    const float* memory  = (const float*)d_in[1];
    const float* embed   = (const float*)d_in[2];
    const float* Wq      = (const float*)d_in[3];
    const float* Wkv     = (const float*)d_in[4];
    const float* Wr      = (const float*)d_in[5];
    const float* Wo      = (const float*)d_in[6];
    const float* bq      = (const float*)d_in[7];
    const float* bkv     = (const float*)d_in[8];
    const float* br      = (const float*)d_in[9];
    const float* bo      = (const float*)d_in[10];
    const float* bias_c  = (const float*)d_in[11];
    const float* bias_r  = (const float*)d_in[12];
    const float* ln1_g   = (const float*)d_in[13];
    const float* ln1_b   = (const float*)d_in[14];
    const float* W1      = (const float*)d_in[15];
    const float* b1      = (const float*)d_in[16];
    const float* W2      = (const float*)d_in[17];
    const float* b2      = (const float*)d_in[18];
    const float* ln2_g   = (const float*)d_in[19];
    const float* ln2_b   = (const float*)d_in[20];
    const float* Wout    = (const float*)d_in[21];
    const float* bout    = (const float*)d_in[22];
    float* out = (float*)d_out;

    float *x, *ac, *ar, *tmp, *h1;
    cudaGetSymbolAddress((void**)&x,   g_x);
    cudaGetSymbolAddress((void**)&ac,  g_ac);
    cudaGetSymbolAddress((void**)&ar,  g_ar);
    cudaGetSymbolAddress((void**)&tmp, g_tmp);
    cudaGetSymbolAddress((void**)&h1,  g_h1);

    bf16 *xh,*xl,*fullh,*fulll,*relh,*rell;
    bf16 *qch,*qcl,*qrh,*qrl,*kvh,*kvl,*rh,*rl,*ph,*pl,*vth,*vtl;
    bf16 *ctxh,*ctxl,*h1h,*h1l,*ffh,*ffl;
    __half *h2hh,*h2lh,*WoutH;
    cudaGetSymbolAddress((void**)&xh, g_xh);       cudaGetSymbolAddress((void**)&xl, g_xl);
    cudaGetSymbolAddress((void**)&fullh, g_fullh); cudaGetSymbolAddress((void**)&fulll, g_fulll);
    cudaGetSymbolAddress((void**)&relh, g_relh);   cudaGetSymbolAddress((void**)&rell, g_rell);
    cudaGetSymbolAddress((void**)&qch, g_qch);     cudaGetSymbolAddress((void**)&qcl, g_qcl);
    cudaGetSymbolAddress((void**)&qrh, g_qrh);     cudaGetSymbolAddress((void**)&qrl, g_qrl);
    cudaGetSymbolAddress((void**)&kvh, g_kvh);     cudaGetSymbolAddress((void**)&kvl, g_kvl);
    cudaGetSymbolAddress((void**)&rh, g_rh);       cudaGetSymbolAddress((void**)&rl, g_rl);
    cudaGetSymbolAddress((void**)&ph, g_ph);       cudaGetSymbolAddress((void**)&pl, g_pl);
    cudaGetSymbolAddress((void**)&vth, g_vth);     cudaGetSymbolAddress((void**)&vtl, g_vtl);
    cudaGetSymbolAddress((void**)&ctxh, g_ctxh);   cudaGetSymbolAddress((void**)&ctxl, g_ctxl);
    cudaGetSymbolAddress((void**)&h1h, g_h1h);     cudaGetSymbolAddress((void**)&h1l, g_h1l);
    cudaGetSymbolAddress((void**)&ffh, g_ffh);     cudaGetSymbolAddress((void**)&ffl, g_ffl);
    cudaGetSymbolAddress((void**)&h2hh, g_h2hh);   cudaGetSymbolAddress((void**)&h2lh, g_h2lh);
    cudaGetSymbolAddress((void**)&WoutH, g_WoutH);

    bf16 *WqTh,*WqTl,*WkvTh,*WkvTl,*WrTh,*WrTl,*WoTh,*WoTl,*W1Th,*W1Tl,*W2Th,*W2Tl;
    cudaGetSymbolAddress((void**)&WqTh, g_WqTh);   cudaGetSymbolAddress((void**)&WqTl, g_WqTl);
    cudaGetSymbolAddress((void**)&WkvTh, g_WkvTh); cudaGetSymbolAddress((void**)&WkvTl, g_WkvTl);
    cudaGetSymbolAddress((void**)&WrTh, g_WrTh);   cudaGetSymbolAddress((void**)&WrTl, g_WrTl);
    cudaGetSymbolAddress((void**)&WoTh, g_WoTh);   cudaGetSymbolAddress((void**)&WoTl, g_WoTl);
    cudaGetSymbolAddress((void**)&W1Th, g_W1Th);   cudaGetSymbolAddress((void**)&W1Tl, g_W1Tl);
    cudaGetSymbolAddress((void**)&W2Th, g_W2Th);   cudaGetSymbolAddress((void**)&W2Tl, g_W2Tl);

    const int M_TOK = BB * SS;      // 2048
    const int M_FULL = BB * KLEN;   // 3200
    dim3 tb(32, 8);

    // Launch order: kv hgemm is MY 4th launch (ncu -s 5 -c 1 lands there,
    // accounting for 2 harness-internal launches).
    // 1) embedding + concat + splits
    {
        long long tot = (long long)BB * KLEN * UU;
        build_full<<<(unsigned)((tot + 255) / 256), 256>>>(tokens, memory, embed,
                                                           x, xh, xl, fullh, fulll);
    }
    // 2) Wkv split
    split_T<<<dim3(2*UU/32, UU/32), tb>>>(Wkv, WkvTh, WkvTl, UU, 2*UU);
    // 3) positional embedding
    {
        long long tot = (long long)KLEN * UU;
        pos_embed<<<(unsigned)((tot + 255) / 256), 256>>>(relh, rell);
    }
    // 4) kv projection  <-- ncu capture target
    hgemm<128,1,3><<<dim3((M_FULL+127)/128, 2*UU/128, 1), 256>>>(
        fullh, fulll, WkvTh, WkvTl, nullptr, kvh, kvl, nullptr, nullptr, bkv, nullptr, nullptr,
        M_FULL, 2*UU, UU, UU, UU, 2*UU, 1, 0,0,0,0,0,0);
    // remaining weight splits
    split_T<<<dim3(UU/32,  UU/32),  tb>>>(Wq,   WqTh,   WqTl,   UU,  UU);
    split_T<<<dim3(UU/32,  UU/32),  tb>>>(Wr,   WrTh,   WrTl,   UU,  UU);
    split_T<<<dim3(UU/32,  UU/32),  tb>>>(Wo,   WoTh,   WoTl,   UU,  UU);
    split_T<<<dim3(FFD/32, UU/32),  tb>>>(W1,   W1Th,   W1Tl,   UU,  FFD);
    split_T<<<dim3(UU/32,  FFD/32), tb>>>(W2,   W2Th,   W2Tl,   FFD, UU);
    split_T_h<<<dim3(NT/32, UU/32), tb>>>(Wout, WoutH, UU, NT);
    // q projection fused with (q+u)/(q+v) splits
    hgemm<128,3,3><<<dim3(M_TOK/128, UU/128, 1), 256>>>(
        xh, xl, WqTh, WqTl, nullptr, qch, qcl, qrh, qrl, bq, bias_c, bias_r,
        M_TOK, UU, UU, UU, UU, UU, 1, 0,0,0,0,0,0);
    // r projection
    hgemm<128,1,3><<<dim3((KLEN+127)/128, UU/128, 1), 256>>>(
        relh, rell, WrTh, WrTl, nullptr, rh, rl, nullptr, nullptr, br, nullptr, nullptr,
        KLEN, UU, UU, UU, UU, UU, 1, 0,0,0,0,0,0);
    // scores (batched over b,h)
    {
        dim3 grid(SS / 128, (KLEN + 127) / 128, BB * HH);
        hgemm<128,0,3><<<grid, 256>>>(qch, qcl, kvh, kvl, ac, nullptr, nullptr, nullptr, nullptr,
            nullptr, nullptr, nullptr,
            SS, KLEN, DD, UU, 2*UU, KLEN, HH,
            (long long)SS*UU, 64,
            (long long)KLEN*2*UU, 64,
            (long long)HH*SS*KLEN, (long long)SS*KLEN);
        hgemm<128,0,3><<<grid, 256>>>(qrh, qrl, rh, rl, ar, nullptr, nullptr, nullptr, nullptr,
            nullptr, nullptr, nullptr,
            SS, KLEN, DD, UU, UU, KLEN, HH,
            (long long)SS*UU, 64,
            0, 64,
            (long long)HH*SS*KLEN, (long long)SS*KLEN);
    }
    // fused rel-shift + mask + softmax -> split P
    {
        dim3 grid(SS, BB * HH);
        attn_softmax<<<grid, 256>>>(ac, ar, ph, pl);
    }
    // V^T per head
    {
        dim3 grid(KLEN / 32, DD / 32, BB * HH);
        transpose_v<<<grid, tb>>>(kvh, kvl, vth, vtl);
    }
    // ctx = P @ V^T
    {
        dim3 grid(SS / 128, 1, BB * HH);
        hgemm<64,1,3><<<grid, 256>>>(ph, pl, vth, vtl, nullptr, ctxh, ctxl, nullptr, nullptr,
            nullptr, nullptr, nullptr,
            SS, DD, KLEN, KLEN, KLEN, UU, HH,
            (long long)HH*SS*KLEN, (long long)SS*KLEN,
            (long long)HH*DD*KLEN, (long long)DD*KLEN,
            (long long)SS*UU, 64);
    }
    // attention out projection + LN1 (bf16 splits for FF)
    hgemm<128,0,3><<<dim3(M_TOK/128, UU/128, 1), 256>>>(
        ctxh, ctxl, WoTh, WoTl, tmp, nullptr, nullptr, nullptr, nullptr, bo, nullptr, nullptr,
        M_TOK, UU, UU, UU, UU, UU, 1, 0,0,0,0,0,0);
    add_ln<bf16><<<M_TOK, 256>>>(x, tmp, ln1_g, ln1_b, h1, h1h, h1l);
    // FF
    hgemm<128,2,3><<<dim3(M_TOK/128, FFD/128, 1), 256>>>(
        h1h, h1l, W1Th, W1Tl, nullptr, ffh, ffl, nullptr, nullptr, b1, nullptr, nullptr,
        M_TOK, FFD, UU, UU, UU, FFD, 1, 0,0,0,0,0,0);
    hgemm<128,0,3><<<dim3(M_TOK/128, UU/128, 1), 256>>>(
        ffh, ffl, W2Th, W2Tl, tmp, nullptr, nullptr, nullptr, nullptr, b2, nullptr, nullptr,
        M_TOK, UU, FFD, FFD, FFD, UU, 1, 0,0,0,0,0,0);
    // LN2 emits fp16 hi/lo for the 2-pass logits GEMM
    add_ln<__half><<<M_TOK, 256>>>(h1, tmp, ln2_g, ln2_b, nullptr, h2hh, h2lh);
    // logits: fp16 2-pass (A = h2 hi+lo fp16, B = Wout single fp16)
    hgemm<128,0,2><<<dim3(M_TOK/128, NT/128, 1), 256>>>(
        (const bf16*)h2hh, (const bf16*)h2lh, (const bf16*)WoutH, nullptr,
        out, nullptr, nullptr, nullptr, nullptr, bout, nullptr, nullptr,
        M_TOK, NT, UU, UU, UU, NT, 1, 0,0,0,0,0,0);
    softmax_rows<<<M_TOK, 512>>>(out, NT);
}

// round 8
// speedup vs baseline: 1.3028x; 1.1076x over previous
#include <cuda_runtime.h>
#include <cuda_bf16.h>
#include <cuda_fp16.h>
#include <math.h>
#include <stdint.h>

// ---------------- problem constants ----------------
#define BB 2
#define SS 1024
#define UU 1024
#define HH 16
#define DD 64
#define NT 32000
#define MEMLEN 576
#define FFD 4096
#define KLEN 1600   // MEM + S
#define VOCAB 1024

typedef __nv_bfloat16 bf16;

// ---------------- scratch (device globals; no allocation allowed) ----------------
__device__ float g_ac  [(size_t)BB*HH*SS*KLEN];
__device__ float g_ar  [(size_t)BB*HH*SS*KLEN];
__device__ float g_x   [(size_t)BB*SS*UU];
__device__ float g_tmp [(size_t)BB*SS*UU];
__device__ float g_h1  [(size_t)BB*SS*UU];

__device__ bf16 g_xh   [(size_t)BB*SS*UU],   g_xl   [(size_t)BB*SS*UU];
__device__ bf16 g_fullh[(size_t)BB*KLEN*UU], g_fulll[(size_t)BB*KLEN*UU];
__device__ bf16 g_relh [(size_t)KLEN*UU],    g_rell [(size_t)KLEN*UU];
__device__ bf16 g_qch  [(size_t)BB*SS*UU],   g_qcl  [(size_t)BB*SS*UU];
__device__ bf16 g_qrh  [(size_t)BB*SS*UU],   g_qrl  [(size_t)BB*SS*UU];
__device__ bf16 g_kvh  [(size_t)BB*KLEN*2*UU], g_kvl [(size_t)BB*KLEN*2*UU];
__device__ bf16 g_rh   [(size_t)KLEN*UU],    g_rl   [(size_t)KLEN*UU];
__device__ bf16 g_ph   [(size_t)BB*HH*SS*KLEN], g_pl [(size_t)BB*HH*SS*KLEN];
__device__ bf16 g_vth  [(size_t)BB*HH*DD*KLEN], g_vtl[(size_t)BB*HH*DD*KLEN];
__device__ bf16 g_ctxh [(size_t)BB*SS*UU],   g_ctxl [(size_t)BB*SS*UU];
__device__ bf16 g_h1h  [(size_t)BB*SS*UU],   g_h1l  [(size_t)BB*SS*UU];
__device__ bf16 g_ffh  [(size_t)BB*SS*FFD],  g_ffl  [(size_t)BB*SS*FFD];
// fp16 buffers for the 2-pass logits path
__device__ __half g_h2hh[(size_t)BB*SS*UU],  g_h2lh [(size_t)BB*SS*UU];
__device__ __half g_WoutH[(size_t)NT*UU];
// transposed weights [N,K] bf16 hi/lo
__device__ bf16 g_WqTh [(size_t)UU*UU],    g_WqTl [(size_t)UU*UU];
__device__ bf16 g_WkvTh[(size_t)2*UU*UU],  g_WkvTl[(size_t)2*UU*UU];
__device__ bf16 g_WrTh [(size_t)UU*UU],    g_WrTl [(size_t)UU*UU];
__device__ bf16 g_WoTh [(size_t)UU*UU],    g_WoTl [(size_t)UU*UU];
__device__ bf16 g_W1Th [(size_t)FFD*UU],   g_W1Tl [(size_t)FFD*UU];
__device__ bf16 g_W2Th [(size_t)UU*FFD],   g_W2Tl [(size_t)UU*FFD];

// ---------------- helpers ----------------
__device__ __forceinline__ uint32_t smem_u32(const void* p) {
    uint32_t a;
    asm("{ .reg .u64 t; cvta.to.shared.u64 t, %1; cvt.u32.u64 %0, t; }" : "=r"(a) : "l"(p));
    return a;
}
__device__ __forceinline__ void split_val(float v, bf16& h, bf16& l) {
    h = __float2bfloat16(v);
    l = __float2bfloat16(v - __bfloat162float(h));
}
__device__ __forceinline__ void split_to(float v, bf16& h, bf16& l) {
    h = __float2bfloat16(v);
    l = __float2bfloat16(v - __bfloat162float(h));
}
__device__ __forceinline__ void split_to(float v, __half& h, __half& l) {
    h = __float2half(v);
    l = __float2half(v - __half2float(h));
}
__device__ __forceinline__ void cp16(uint32_t dst, const void* src) {
    asm volatile("cp.async.cg.shared.global [%0], [%1], 16;" :: "r"(dst), "l"(src));
}
__device__ __forceinline__ void ldx4(uint32_t* r, uint32_t addr) {
    asm volatile("ldmatrix.sync.aligned.m8n8.x4.shared.b16 {%0,%1,%2,%3}, [%4];"
                 : "=r"(r[0]), "=r"(r[1]), "=r"(r[2]), "=r"(r[3]) : "r"(addr));
}
__device__ __forceinline__ void mma_bf(float* c, const uint32_t* a, const uint32_t* b) {
    asm volatile("mma.sync.aligned.m16n8k16.row.col.f32.bf16.bf16.f32 "
                 "{%0,%1,%2,%3}, {%4,%5,%6,%7}, {%8,%9}, {%0,%1,%2,%3};"
                 : "+f"(c[0]), "+f"(c[1]), "+f"(c[2]), "+f"(c[3])
                 : "r"(a[0]), "r"(a[1]), "r"(a[2]), "r"(a[3]), "r"(b[0]), "r"(b[1]));
}
__device__ __forceinline__ void mma_fp(float* c, const uint32_t* a, const uint32_t* b) {
    asm volatile("mma.sync.aligned.m16n8k16.row.col.f32.f16.f16.f32 "
                 "{%0,%1,%2,%3}, {%4,%5,%6,%7}, {%8,%9}, {%0,%1,%2,%3};"
                 : "+f"(c[0]), "+f"(c[1]), "+f"(c[2]), "+f"(c[3])
                 : "r"(a[0]), "r"(a[1]), "r"(a[2]), "r"(a[3]), "r"(b[0]), "r"(b[1]));
}

// ---------------- generalized HMMA split GEMM ----------------
// PASS=3 (bf16): C = (Ah+Al) @ (Bh+Bl)^T via hh + hl + lh.
// PASS=2 (fp16): C = (Ah+Al) @ Bh^T via hh + lh.
// 4-stage cp.async pipeline, ONE __syncthreads per K16 chunk.
// OUT: 0 = fp32 C (+bias); 1 = split bf16; 2 = relu + split; 3 = dual-bias split.
template<int BN, int OUT, int PASS>
__global__ __launch_bounds__(256)
void hgemm(const bf16* __restrict__ Ah, const bf16* __restrict__ Al,
           const bf16* __restrict__ Bh, const bf16* __restrict__ Bl,
           float* __restrict__ C, bf16* __restrict__ Ch, bf16* __restrict__ Cl,
           bf16* __restrict__ Dh, bf16* __restrict__ Dl,
           const float* __restrict__ bias,
           const float* __restrict__ bias2, const float* __restrict__ bias3,
           int M, int N, int K, int lda, int ldb, int ldc, int Z2,
           long long sA1, long long sA2, long long sB1, long long sB2,
           long long sC1, long long sC2)
{
    constexpr int BSTR = BN * 32;
    constexpr int STAGE = 8192 + (PASS == 3 ? 2 : 1) * BSTR;
    constexpr int MT = (BN == 128) ? 4 : 2;
    constexpr int NTP = BN / 64;                 // 2 for BN=128, 1 for BN=64 (per n_w=32: 2 pairs)
    extern __shared__ __align__(128) char sm[];
    const uint32_t smb = smem_u32(sm);
    const int tid = threadIdx.x, wid = tid >> 5, lane = tid & 31;
    const int m0 = blockIdx.x * 128, n0 = blockIdx.y * BN;
    const int m_w = (BN == 128) ? (wid & 1) * 64 : (wid & 3) * 32;
    const int n_w = (BN == 128) ? (wid >> 1) * 32 : (wid >> 2) * 32;

    const int z = blockIdx.z;
    const int z1 = z / Z2, z2 = z - z1 * Z2;
    Ah += z1 * sA1 + z2 * sA2;  Al += z1 * sA1 + z2 * sA2;
    Bh += z1 * sB1 + z2 * sB2;
    if (PASS == 3) Bl += z1 * sB1 + z2 * sB2;
    const long long cbase = z1 * sC1 + z2 * sC2;

    const int lr = tid >> 1, lc = tid & 1;
    const uint32_t so = (uint32_t)(lr * 32 + ((lc ^ ((lr >> 2) & 1)) << 4));
    const int ga = min(m0 + lr, M - 1);
    const long long aoff = (long long)ga * lda + lc * 8;
    const bool bdo = (BN == 128) || (tid < 128);
    const int gb = min(n0 + lr, N - 1);
    const long long boff = (long long)gb * ldb + lc * 8;

    float acc[MT][4][4];
    #pragma unroll
    for (int i = 0; i < MT; i++)
        #pragma unroll
        for (int j = 0; j < 4; j++)
            #pragma unroll
            for (int k = 0; k < 4; k++) acc[i][j][k] = 0.f;

    const int NC = K / 16;

    // prologue: stages 0,1,2
    #pragma unroll
    for (int pc = 0; pc < 3; pc++) {
        const uint32_t st = smb + pc * STAGE;
        cp16(st + so,        Ah + aoff + pc * 16);
        cp16(st + 4096 + so, Al + aoff + pc * 16);
        if (bdo) {
            cp16(st + 8192 + so, Bh + boff + pc * 16);
            if (PASS == 3) cp16(st + 8192 + BSTR + so, Bl + boff + pc * 16);
        }
        asm volatile("cp.async.commit_group;");
    }

    const int rr = lane & 15, ccq = lane >> 4;
    // B ldx4 merge: 16-row group; bit4 of lane selects row octet, bit3 selects k-half
    const int rbq = (lane & 7) | ((lane & 16) >> 1);
    const int cbq = (lane >> 3) & 1;

    for (int c = 0; c < NC; c++) {
        asm volatile("cp.async.wait_group 2;");
        __syncthreads();
        if (c + 3 < NC) {
            const uint32_t st = smb + ((c + 3) & 3) * STAGE;
            const long long k0 = (long long)(c + 3) * 16;
            cp16(st + so,        Ah + aoff + k0);
            cp16(st + 4096 + so, Al + aoff + k0);
            if (bdo) {
                cp16(st + 8192 + so, Bh + boff + k0);
                if (PASS == 3) cp16(st + 8192 + BSTR + so, Bl + boff + k0);
            }
        }
        asm volatile("cp.async.commit_group;");

        const uint32_t st = smb + (c & 3) * STAGE;
        uint32_t ah[MT][4], al[MT][4], bh[2][4], bl[2][4];
        #pragma unroll
        for (int mt = 0; mt < MT; mt++) {
            int R = m_w + mt * 16 + rr;
            uint32_t ad = st + R * 32 + ((ccq ^ ((R >> 2) & 1)) << 4);
            ldx4(ah[mt], ad);
            ldx4(al[mt], ad + 4096);
        }
        #pragma unroll
        for (int np = 0; np < 2; np++) {
            int Nr = n_w + np * 16 + rbq;
            uint32_t bd = st + 8192 + Nr * 32 + ((cbq ^ ((Nr >> 2) & 1)) << 4);
            ldx4(bh[np], bd);
            if (PASS == 3) ldx4(bl[np], bd + BSTR);
        }
        #pragma unroll
        for (int mt = 0; mt < MT; mt++)
            #pragma unroll
            for (int nt = 0; nt < 4; nt++) {
                const uint32_t* bhp = &bh[nt >> 1][(nt & 1) * 2];
                if (PASS == 3) {
                    const uint32_t* blp = &bl[nt >> 1][(nt & 1) * 2];
                    mma_bf(acc[mt][nt], ah[mt], bhp);
                    mma_bf(acc[mt][nt], ah[mt], blp);
                    mma_bf(acc[mt][nt], al[mt], bhp);
                } else {
                    mma_fp(acc[mt][nt], ah[mt], bhp);
                    mma_fp(acc[mt][nt], al[mt], bhp);
                }
            }
    }

    // ---- epilogue ----
    #pragma unroll
    for (int mt = 0; mt < MT; mt++) {
        int gm0 = m0 + m_w + mt * 16 + (lane >> 2);
        #pragma unroll
        for (int nt = 0; nt < 4; nt++) {
            int gn = n0 + n_w + nt * 8 + (lane & 3) * 2;
            if (gn >= N) continue;
            float bx = 0.f, by = 0.f;
            if (bias) { float2 bv = *(const float2*)(bias + gn); bx = bv.x; by = bv.y; }
            float v0 = acc[mt][nt][0] + bx;
            float v1 = acc[mt][nt][1] + by;
            float v2 = acc[mt][nt][2] + bx;
            float v3 = acc[mt][nt][3] + by;
            if (OUT == 0) {
                if (gm0 < M) {
                    float2 w; w.x = v0; w.y = v1;
                    *(float2*)(C + cbase + (long long)gm0 * ldc + gn) = w;
                }
                if (gm0 + 8 < M) {
                    float2 w; w.x = v2; w.y = v3;
                    *(float2*)(C + cbase + (long long)(gm0 + 8) * ldc + gn) = w;
                }
            } else if (OUT == 3) {
                float2 b2 = *(const float2*)(bias2 + gn);
                float2 b3 = *(const float2*)(bias3 + gn);
                bf16 h0, l0, h1, l1;
                if (gm0 < M) {
                    long long o = cbase + (long long)gm0 * ldc + gn;
                    split_val(v0 + b2.x, h0, l0); split_val(v1 + b2.y, h1, l1);
                    __nv_bfloat162 ph; ph.x = h0; ph.y = h1;
                    __nv_bfloat162 pl; pl.x = l0; pl.y = l1;
                    *(__nv_bfloat162*)(Ch + o) = ph; *(__nv_bfloat162*)(Cl + o) = pl;
                    split_val(v0 + b3.x, h0, l0); split_val(v1 + b3.y, h1, l1);
                    ph.x = h0; ph.y = h1; pl.x = l0; pl.y = l1;
                    *(__nv_bfloat162*)(Dh + o) = ph; *(__nv_bfloat162*)(Dl + o) = pl;
                }
                if (gm0 + 8 < M) {
                    long long o = cbase + (long long)(gm0 + 8) * ldc + gn;
                    split_val(v2 + b2.x, h0, l0); split_val(v3 + b2.y, h1, l1);
                    __nv_bfloat162 ph; ph.x = h0; ph.y = h1;
                    __nv_bfloat162 pl; pl.x = l0; pl.y = l1;
                    *(__nv_bfloat162*)(Ch + o) = ph; *(__nv_bfloat162*)(Cl + o) = pl;
                    split_val(v2 + b3.x, h0, l0); split_val(v3 + b3.y, h1, l1);
                    ph.x = h0; ph.y = h1; pl.x = l0; pl.y = l1;
                    *(__nv_bfloat162*)(Dh + o) = ph; *(__nv_bfloat162*)(Dl + o) = pl;
                }
            } else {
                if (OUT == 2) {
                    v0 = fmaxf(v0, 0.f); v1 = fmaxf(v1, 0.f);
                    v2 = fmaxf(v2, 0.f); v3 = fmaxf(v3, 0.f);
                }
                bf16 h0, l0, h1, l1;
                if (gm0 < M) {
                    long long o = cbase + (long long)gm0 * ldc + gn;
                    split_val(v0, h0, l0); split_val(v1, h1, l1);
                    __nv_bfloat162 ph; ph.x = h0; ph.y = h1;
                    __nv_bfloat162 pl; pl.x = l0; pl.y = l1;
                    *(__nv_bfloat162*)(Ch + o) = ph; *(__nv_bfloat162*)(Cl + o) = pl;
                }
                if (gm0 + 8 < M) {
                    long long o = cbase + (long long)(gm0 + 8) * ldc + gn;
                    split_val(v2, h0, l0); split_val(v3, h1, l1);
                    __nv_bfloat162 ph; ph.x = h0; ph.y = h1;
                    __nv_bfloat162 pl; pl.x = l0; pl.y = l1;
                    *(__nv_bfloat162*)(Ch + o) = ph; *(__nv_bfloat162*)(Cl + o) = pl;
                }
            }
        }
    }
}

// ---------------- reductions ----------------
__device__ __forceinline__ float block_reduce_sum(float v) {
    __shared__ float sm[16];
    __syncthreads();
    #pragma unroll
    for (int o = 16; o > 0; o >>= 1) v += __shfl_xor_sync(0xffffffffu, v, o);
    if ((threadIdx.x & 31) == 0) sm[threadIdx.x >> 5] = v;
    __syncthreads();
    if (threadIdx.x < 32) {
        float x = (threadIdx.x < (blockDim.x >> 5)) ? sm[threadIdx.x] : 0.f;
        #pragma unroll
        for (int o = 8; o > 0; o >>= 1) x += __shfl_xor_sync(0xffffffffu, x, o);
        if (threadIdx.x == 0) sm[0] = x;
    }
    __syncthreads();
    return sm[0];
}
__device__ __forceinline__ float block_reduce_max(float v) {
    __shared__ float sm[16];
    __syncthreads();
    #pragma unroll
    for (int o = 16; o > 0; o >>= 1) v = fmaxf(v, __shfl_xor_sync(0xffffffffu, v, o));
    if ((threadIdx.x & 31) == 0) sm[threadIdx.x >> 5] = v;
    __syncthreads();
    if (threadIdx.x < 32) {
        float x = (threadIdx.x < (blockDim.x >> 5)) ? sm[threadIdx.x] : -3.4e38f;
        #pragma unroll
        for (int o = 8; o > 0; o >>= 1) x = fmaxf(x, __shfl_xor_sync(0xffffffffu, x, o));
        if (threadIdx.x == 0) sm[0] = x;
    }
    __syncthreads();
    return sm[0];
}

// ---------------- small kernels ----------------
__global__ void build_full(const int* __restrict__ tokens,
                           const float* __restrict__ memory,
                           const float* __restrict__ embed,
                           float* __restrict__ x,
                           bf16* __restrict__ xh, bf16* __restrict__ xl,
                           bf16* __restrict__ fullh, bf16* __restrict__ fulll)
{
    long long idx = (long long)blockIdx.x * 256 + threadIdx.x;
    const long long tot = (long long)BB * KLEN * UU;
    if (idx >= tot) return;
    int u = (int)(idx % UU);
    long long t = idx / UU;
    int j = (int)(t % KLEN);
    int b = (int)(t / KLEN);
    float v;
    if (j < MEMLEN) {
        v = memory[((long long)b * MEMLEN + j) * UU + u];
    } else {
        int s = j - MEMLEN;
        int tok = tokens[b * SS + s];
        v = embed[(long long)tok * UU + u] * 32.0f;  // sqrt(1024)
        long long xo = ((long long)b * SS + s) * UU + u;
        x[xo] = v;
        bf16 h, l; split_val(v, h, l);
        xh[xo] = h; xl[xo] = l;
    }
    bf16 h, l; split_val(v, h, l);
    fullh[idx] = h; fulll[idx] = l;
}

__global__ void pos_embed(bf16* __restrict__ relh, bf16* __restrict__ rell)
{
    long long idx = (long long)blockIdx.x * 256 + threadIdx.x;
    if (idx >= (long long)KLEN * UU) return;
    int u = (int)(idx % UU);
    int jj = (int)(idx / UU);
    float pos = (float)(KLEN - 1 - jj);
    int i2 = (u < UU / 2) ? u : (u - UU / 2);
    float expo = ((float)(2 * i2)) / (float)UU;
    float invf = expf(-expo * 9.210340371976184f);  // ln(10000)
    float ang = pos * invf;
    float v = (u < UU / 2) ? sinf(ang) : cosf(ang);
    bf16 h, l; split_val(v, h, l);
    relh[idx] = h; rell[idx] = l;
}

// transpose + split: W[K,N] fp32 -> hi/lo[N,K] bf16
__global__ void split_T(const float* __restrict__ W, bf16* __restrict__ hi,
                        bf16* __restrict__ lo, int K, int N)
{
    __shared__ float t[32][33];
    int n0 = blockIdx.x * 32, k0 = blockIdx.y * 32;
    #pragma unroll
    for (int i = 0; i < 32; i += 8)
        t[threadIdx.y + i][threadIdx.x] =
            W[(long long)(k0 + threadIdx.y + i) * N + n0 + threadIdx.x];
    __syncthreads();
    #pragma unroll
    for (int i = 0; i < 32; i += 8) {
        float v = t[threadIdx.x][threadIdx.y + i];
        long long o = (long long)(n0 + threadIdx.y + i) * K + k0 + threadIdx.x;
        bf16 h, l; split_val(v, h, l);
        hi[o] = h; lo[o] = l;
    }
}

// transpose: W[K,N] fp32 -> single fp16 [N,K]
__global__ void split_T_h(const float* __restrict__ W, __half* __restrict__ hi,
                          int K, int N)
{
    __shared__ float t[32][33];
    int n0 = blockIdx.x * 32, k0 = blockIdx.y * 32;
    #pragma unroll
    for (int i = 0; i < 32; i += 8)
        t[threadIdx.y + i][threadIdx.x] =
            W[(long long)(k0 + threadIdx.y + i) * N + n0 + threadIdx.x];
    __syncthreads();
    #pragma unroll
    for (int i = 0; i < 32; i += 8) {
        float v = t[threadIdx.x][threadIdx.y + i];
        long long o = (long long)(n0 + threadIdx.y + i) * K + k0 + threadIdx.x;
        hi[o] = __float2half(v);
    }
}

// V^T per head: vt[(b*H+h), d, j] = kv[b, j, U + h*64 + d]
__global__ void transpose_v(const bf16* __restrict__ kvh, const bf16* __restrict__ kvl,
                            bf16* __restrict__ vth, bf16* __restrict__ vtl)
{
    __shared__ bf16 th[32][33], tl[32][33];
    int z = blockIdx.z;
    int b = z / HH, h = z % HH;
    int j0 = blockIdx.x * 32, d0 = blockIdx.y * 32;
    int tx = threadIdx.x, ty = threadIdx.y;
    #pragma unroll
    for (int i = 0; i < 32; i += 8) {
        long long src = ((long long)b * KLEN + j0 + ty + i) * (2 * UU) + UU + h * 64 + d0 + tx;
        th[ty + i][tx] = kvh[src];
        tl[ty + i][tx] = kvl[src];
    }
    __syncthreads();
    #pragma unroll
    for (int i = 0; i < 32; i += 8) {
        long long dst = ((long long)z * DD + d0 + ty + i) * KLEN + j0 + tx;
        vth[dst] = th[tx][ty + i];
        vtl[dst] = tl[tx][ty + i];
    }
}

// mask + rel-shift + softmax; writes P as split bf16 (zero tail)
__global__ __launch_bounds__(256)
void attn_softmax(const float* __restrict__ ac, const float* __restrict__ ar,
                  bf16* __restrict__ ph, bf16* __restrict__ pl)
{
    int i = blockIdx.x;
    long long z = blockIdx.y;
    const float* arow = ac + (z * SS + i) * (long long)KLEN;
    const float* rrow = ar + (z * SS + i) * (long long)KLEN;
    bf16* phr = ph + (z * SS + i) * (long long)KLEN;
    bf16* plr = pl + (z * SS + i) * (long long)KLEN;
    int lim = i + MEMLEN;
    int shift = SS - 1 - i;
    int tid = threadIdx.x;

    float vals[7];
    int cnt = 0;
    float lmax = -3.4e38f;
    for (int j = tid; j <= lim; j += 256) {
        float v = (arow[j] + rrow[j + shift]) * 0.125f;
        vals[cnt++] = v;
        lmax = fmaxf(lmax, v);
    }
    float m = block_reduce_max(lmax);
    float lsum = 0.f;
    for (int t = 0; t < cnt; t++) {
        float e = expf(vals[t] - m);
        vals[t] = e;
        lsum += e;
    }
    float s = block_reduce_sum(lsum);
    float inv = 1.f / s;
    cnt = 0;
    for (int j = tid; j <= lim; j += 256) {
        float p = vals[cnt++] * inv;
        bf16 h, l; split_val(p, h, l);
        phr[j] = h; plr[j] = l;
    }
    bf16 z0 = __float2bfloat16(0.f);
    for (int j = lim + 1 + tid; j < KLEN; j += 256) { phr[j] = z0; plr[j] = z0; }
}

// add + LayerNorm; emits fp32 (optional) plus split pair of type T
template<typename T>
__global__ __launch_bounds__(256)
void add_ln(const float* __restrict__ a, const float* __restrict__ b,
            const float* __restrict__ g, const float* __restrict__ beta,
            float* __restrict__ out, T* __restrict__ oh, T* __restrict__ ol)
{
    long long row = blockIdx.x;
    const float* pa = a + row * UU;
    const float* pb = b + row * UU;
    int tid = threadIdx.x;
    float vals[4];
    float s = 0.f, ss = 0.f;
    #pragma unroll
    for (int t = 0; t < 4; t++) {
        int idx = tid * 4 + t;
        float v = pa[idx] + pb[idx];
        vals[t] = v;
        s += v;
        ss += v * v;
    }
    s = block_reduce_sum(s);
    ss = block_reduce_sum(ss);
    float mean = s * (1.f / UU);
    float var = fmaxf(ss * (1.f / UU) - mean * mean, 0.f);
    float rstd = rsqrtf(var + 1e-5f);
    #pragma unroll
    for (int t = 0; t < 4; t++) {
        int idx = tid * 4 + t;
        float v = (vals[t] - mean) * rstd * g[idx] + beta[idx];
        if (out) out[row * UU + idx] = v;
        T h, l; split_to(v, h, l);
        oh[row * UU + idx] = h; ol[row * UU + idx] = l;
    }
}

// online-softmax over vocab rows, in place
__global__ __launch_bounds__(512)
void softmax_rows(float* __restrict__ x, int N)
{
    __shared__ float smm[16], sms[16];
    long long row = blockIdx.x;
    float* p = x + row * (long long)N;
    int tid = threadIdx.x;
    float m = -3.4e38f, s = 0.f;
    for (int j = tid; j < N; j += 512) {
        float v = p[j];
        if (v > m) { s = s * expf(m - v) + 1.f; m = v; }
        else       { s += expf(v - m); }
    }
    #pragma unroll
    for (int o = 16; o > 0; o >>= 1) {
        float m2 = __shfl_xor_sync(0xffffffffu, m, o);
        float s2 = __shfl_xor_sync(0xffffffffu, s, o);
        float M = fmaxf(m, m2);
        s = s * expf(m - M) + s2 * expf(m2 - M);
        m = M;
    }
    if ((tid & 31) == 0) { smm[tid >> 5] = m; sms[tid >> 5] = s; }
    __syncthreads();
    if (tid < 32) {
        float mm = (tid < 16) ? smm[tid] : -3.4e38f;
        float ssv = (tid < 16) ? sms[tid] : 0.f;
        #pragma unroll
        for (int o = 8; o > 0; o >>= 1) {
            float m2 = __shfl_xor_sync(0xffffffffu, mm, o);
            float s2 = __shfl_xor_sync(0xffffffffu, ssv, o);
            float M = fmaxf(mm, m2);
            ssv = ssv * expf(mm - M) + s2 * expf(m2 - M);
            mm = M;
        }
        if (tid == 0) { smm[0] = mm; sms[0] = ssv; }
    }
    __syncthreads();
    float M = smm[0];
    float inv = 1.f / sms[0];
    for (int j = tid; j < N; j += 512) p[j] = expf(p[j] - M) * inv;
}

// ---------------- host ----------------
#define SMEM_OF(BN, PASS) (4 * (8192 + ((PASS) == 3 ? 2 : 1) * (BN) * 32))

extern "C" void kernel_launch(void* const* d_in, const int* in_sizes, int n_in,
                              void* d_out, int out_size)
{
    const int*   tokens  = (const int*)  d_in[0];
    const float* memory  = (const float*)d_in[1];
    const float* embed   = (const float*)d_in[2];
    const float* Wq      = (const float*)d_in[3];
    const float* Wkv     = (const float*)d_in[4];
    const float* Wr      = (const float*)d_in[5];
    const float* Wo      = (const float*)d_in[6];
    const float* bq      = (const float*)d_in[7];
    const float* bkv     = (const float*)d_in[8];
    const float* br      = (const float*)d_in[9];
    const float* bo      = (const float*)d_in[10];
    const float* bias_c  = (const float*)d_in[11];
    const float* bias_r  = (const float*)d_in[12];
    const float* ln1_g   = (const float*)d_in[13];
    const float* ln1_b   = (const float*)d_in[14];
    const float* W1      = (const float*)d_in[15];
    const float* b1      = (const float*)d_in[16];
    const float* W2      = (const float*)d_in[17];
    const float* b2      = (const float*)d_in[18];
    const float* ln2_g   = (const float*)d_in[19];
    const float* ln2_b   = (const float*)d_in[20];
    const float* Wout    = (const float*)d_in[21];
    const float* bout    = (const float*)d_in[22];
    float* out = (float*)d_out;

    static bool s_attr = false;
    if (!s_attr) {
        cudaFuncSetAttribute(hgemm<128,0,3>, cudaFuncAttributeMaxDynamicSharedMemorySize, SMEM_OF(128,3));
        cudaFuncSetAttribute(hgemm<128,1,3>, cudaFuncAttributeMaxDynamicSharedMemorySize, SMEM_OF(128,3));
        cudaFuncSetAttribute(hgemm<128,2,3>, cudaFuncAttributeMaxDynamicSharedMemorySize, SMEM_OF(128,3));
        cudaFuncSetAttribute(hgemm<128,3,3>, cudaFuncAttributeMaxDynamicSharedMemorySize, SMEM_OF(128,3));
        cudaFuncSetAttribute(hgemm<64,1,3>,  cudaFuncAttributeMaxDynamicSharedMemorySize, SMEM_OF(64,3));
        cudaFuncSetAttribute(hgemm<128,0,2>, cudaFuncAttributeMaxDynamicSharedMemorySize, SMEM_OF(128,2));
        s_attr = true;
    }

    float *x, *ac, *ar, *tmp, *h1;
    cudaGetSymbolAddress((void**)&x,   g_x);
    cudaGetSymbolAddress((void**)&ac,  g_ac);
    cudaGetSymbolAddress((void**)&ar,  g_ar);
    cudaGetSymbolAddress((void**)&tmp, g_tmp);
    cudaGetSymbolAddress((void**)&h1,  g_h1);

    bf16 *xh,*xl,*fullh,*fulll,*relh,*rell;
    bf16 *qch,*qcl,*qrh,*qrl,*kvh,*kvl,*rh,*rl,*ph,*pl,*vth,*vtl;
    bf16 *ctxh,*ctxl,*h1h,*h1l,*ffh,*ffl;
    __half *h2hh,*h2lh,*WoutH;
    cudaGetSymbolAddress((void**)&xh, g_xh);       cudaGetSymbolAddress((void**)&xl, g_xl);
    cudaGetSymbolAddress((void**)&fullh, g_fullh); cudaGetSymbolAddress((void**)&fulll, g_fulll);
    cudaGetSymbolAddress((void**)&relh, g_relh);   cudaGetSymbolAddress((void**)&rell, g_rell);
    cudaGetSymbolAddress((void**)&qch, g_qch);     cudaGetSymbolAddress((void**)&qcl, g_qcl);
    cudaGetSymbolAddress((void**)&qrh, g_qrh);     cudaGetSymbolAddress((void**)&qrl, g_qrl);
    cudaGetSymbolAddress((void**)&kvh, g_kvh);     cudaGetSymbolAddress((void**)&kvl, g_kvl);
    cudaGetSymbolAddress((void**)&rh, g_rh);       cudaGetSymbolAddress((void**)&rl, g_rl);
    cudaGetSymbolAddress((void**)&ph, g_ph);       cudaGetSymbolAddress((void**)&pl, g_pl);
    cudaGetSymbolAddress((void**)&vth, g_vth);     cudaGetSymbolAddress((void**)&vtl, g_vtl);
    cudaGetSymbolAddress((void**)&ctxh, g_ctxh);   cudaGetSymbolAddress((void**)&ctxl, g_ctxl);
    cudaGetSymbolAddress((void**)&h1h, g_h1h);     cudaGetSymbolAddress((void**)&h1l, g_h1l);
    cudaGetSymbolAddress((void**)&ffh, g_ffh);     cudaGetSymbolAddress((void**)&ffl, g_ffl);
    cudaGetSymbolAddress((void**)&h2hh, g_h2hh);   cudaGetSymbolAddress((void**)&h2lh, g_h2lh);
    cudaGetSymbolAddress((void**)&WoutH, g_WoutH);

    bf16 *WqTh,*WqTl,*WkvTh,*WkvTl,*WrTh,*WrTl,*WoTh,*WoTl,*W1Th,*W1Tl,*W2Th,*W2Tl;
    cudaGetSymbolAddress((void**)&WqTh, g_WqTh);   cudaGetSymbolAddress((void**)&WqTl, g_WqTl);
    cudaGetSymbolAddress((void**)&WkvTh, g_WkvTh); cudaGetSymbolAddress((void**)&WkvTl, g_WkvTl);
    cudaGetSymbolAddress((void**)&WrTh, g_WrTh);   cudaGetSymbolAddress((void**)&WrTl, g_WrTl);
    cudaGetSymbolAddress((void**)&WoTh, g_WoTh);   cudaGetSymbolAddress((void**)&WoTl, g_WoTl);
    cudaGetSymbolAddress((void**)&W1Th, g_W1Th);   cudaGetSymbolAddress((void**)&W1Tl, g_W1Tl);
    cudaGetSymbolAddress((void**)&W2Th, g_W2Th);   cudaGetSymbolAddress((void**)&W2Tl, g_W2Tl);

    const int M_TOK = BB * SS;      // 2048
    const int M_FULL = BB * KLEN;   // 3200
    dim3 tb(32, 8);

    // 1) embedding + concat + splits
    {
        long long tot = (long long)BB * KLEN * UU;
        build_full<<<(unsigned)((tot + 255) / 256), 256>>>(tokens, memory, embed,
                                                           x, xh, xl, fullh, fulll);
    }
    // 2) Wkv split
    split_T<<<dim3(2*UU/32, UU/32), tb>>>(Wkv, WkvTh, WkvTl, UU, 2*UU);
    // 3) positional embedding
    {
        long long tot = (long long)KLEN * UU;
        pos_embed<<<(unsigned)((tot + 255) / 256), 256>>>(relh, rell);
    }
    // 4) kv projection  <-- ncu capture target (4th launch)
    hgemm<128,1,3><<<dim3((M_FULL+127)/128, 2*UU/128, 1), 256, SMEM_OF(128,3)>>>(
        fullh, fulll, WkvTh, WkvTl, nullptr, kvh, kvl, nullptr, nullptr, bkv, nullptr, nullptr,
        M_FULL, 2*UU, UU, UU, UU, 2*UU, 1, 0,0,0,0,0,0);
    // remaining weight splits
    split_T<<<dim3(UU/32,  UU/32),  tb>>>(Wq,   WqTh,   WqTl,   UU,  UU);
    split_T<<<dim3(UU/32,  UU/32),  tb>>>(Wr,   WrTh,   WrTl,   UU,  UU);
    split_T<<<dim3(UU/32,  UU/32),  tb>>>(Wo,   WoTh,   WoTl,   UU,  UU);
    split_T<<<dim3(FFD/32, UU/32),  tb>>>(W1,   W1Th,   W1Tl,   UU,  FFD);
    split_T<<<dim3(UU/32,  FFD/32), tb>>>(W2,   W2Th,   W2Tl,   FFD, UU);
    split_T_h<<<dim3(NT/32, UU/32), tb>>>(Wout, WoutH, UU, NT);
    // q projection fused with (q+u)/(q+v) splits
    hgemm<128,3,3><<<dim3(M_TOK/128, UU/128, 1), 256, SMEM_OF(128,3)>>>(
        xh, xl, WqTh, WqTl, nullptr, qch, qcl, qrh, qrl, bq, bias_c, bias_r,
        M_TOK, UU, UU, UU, UU, UU, 1, 0,0,0,0,0,0);
    // r projection
    hgemm<128,1,3><<<dim3((KLEN+127)/128, UU/128, 1), 256, SMEM_OF(128,3)>>>(
        relh, rell, WrTh, WrTl, nullptr, rh, rl, nullptr, nullptr, br, nullptr, nullptr,
        KLEN, UU, UU, UU, UU, UU, 1, 0,0,0,0,0,0);
    // scores (batched over b,h)
    {
        dim3 grid(SS / 128, (KLEN + 127) / 128, BB * HH);
        hgemm<128,0,3><<<grid, 256, SMEM_OF(128,3)>>>(qch, qcl, kvh, kvl, ac,
            nullptr, nullptr, nullptr, nullptr, nullptr, nullptr, nullptr,
            SS, KLEN, DD, UU, 2*UU, KLEN, HH,
            (long long)SS*UU, 64,
            (long long)KLEN*2*UU, 64,
            (long long)HH*SS*KLEN, (long long)SS*KLEN);
        hgemm<128,0,3><<<grid, 256, SMEM_OF(128,3)>>>(qrh, qrl, rh, rl, ar,
            nullptr, nullptr, nullptr, nullptr, nullptr, nullptr, nullptr,
            SS, KLEN, DD, UU, UU, KLEN, HH,
            (long long)SS*UU, 64,
            0, 64,
            (long long)HH*SS*KLEN, (long long)SS*KLEN);
    }
    // fused rel-shift + mask + softmax -> split P
    {
        dim3 grid(SS, BB * HH);
        attn_softmax<<<grid, 256>>>(ac, ar, ph, pl);
    }
    // V^T per head
    {
        dim3 grid(KLEN / 32, DD / 32, BB * HH);
        transpose_v<<<grid, tb>>>(kvh, kvl, vth, vtl);
    }
    // ctx = P @ V^T
    {
        dim3 grid(SS / 128, 1, BB * HH);
        hgemm<64,1,3><<<grid, 256, SMEM_OF(64,3)>>>(ph, pl, vth, vtl, nullptr, ctxh, ctxl,
            nullptr, nullptr, nullptr, nullptr, nullptr,
            SS, DD, KLEN, KLEN, KLEN, UU, HH,
            (long long)HH*SS*KLEN, (long long)SS*KLEN,
            (long long)HH*DD*KLEN, (long long)DD*KLEN,
            (long long)SS*UU, 64);
    }
    // attention out projection + LN1
    hgemm<128,0,3><<<dim3(M_TOK/128, UU/128, 1), 256, SMEM_OF(128,3)>>>(
        ctxh, ctxl, WoTh, WoTl, tmp, nullptr, nullptr, nullptr, nullptr, bo, nullptr, nullptr,
        M_TOK, UU, UU, UU, UU, UU, 1, 0,0,0,0,0,0);
    add_ln<bf16><<<M_TOK, 256>>>(x, tmp, ln1_g, ln1_b, h1, h1h, h1l);
    // FF
    hgemm<128,2,3><<<dim3(M_TOK/128, FFD/128, 1), 256, SMEM_OF(128,3)>>>(
        h1h, h1l, W1Th, W1Tl, nullptr, ffh, ffl, nullptr, nullptr, b1, nullptr, nullptr,
        M_TOK, FFD, UU, UU, UU, FFD, 1, 0,0,0,0,0,0);
    hgemm<128,0,3><<<dim3(M_TOK/128, UU/128, 1), 256, SMEM_OF(128,3)>>>(
        ffh, ffl, W2Th, W2Tl, tmp, nullptr, nullptr, nullptr, nullptr, b2, nullptr, nullptr,
        M_TOK, UU, FFD, FFD, FFD, UU, 1, 0,0,0,0,0,0);
    // LN2 emits fp16 hi/lo for the 2-pass logits GEMM
    add_ln<__half><<<M_TOK, 256>>>(h1, tmp, ln2_g, ln2_b, nullptr, h2hh, h2lh);
    // logits: fp16 2-pass
    hgemm<128,0,2><<<dim3(M_TOK/128, NT/128, 1), 256, SMEM_OF(128,2)>>>(
        (const bf16*)h2hh, (const bf16*)h2lh, (const bf16*)WoutH, nullptr,
        out, nullptr, nullptr, nullptr, nullptr, bout, nullptr, nullptr,
        M_TOK, NT, UU, UU, UU, NT, 1, 0,0,0,0,0,0);
    softmax_rows<<<M_TOK, 512>>>(out, NT);
}

// round 9
// speedup vs baseline: 1.3382x; 1.0271x over previous
#include <cuda_runtime.h>
#include <cuda_bf16.h>
#include <cuda_fp16.h>
#include <math.h>
#include <stdint.h>

// ---------------- problem constants ----------------
#define BB 2
#define SS 1024
#define UU 1024
#define HH 16
#define DD 64
#define NT 32000
#define MEMLEN 576
#define FFD 4096
#define KLEN 1600   // MEM + S
#define VOCAB 1024

typedef __nv_bfloat16 bf16;

// ---------------- scratch (device globals; no allocation allowed) ----------------
__device__ float g_ac  [(size_t)BB*HH*SS*KLEN];
__device__ float g_ar  [(size_t)BB*HH*SS*KLEN];
__device__ float g_x   [(size_t)BB*SS*UU];
__device__ float g_tmp [(size_t)BB*SS*UU];
__device__ float g_h1  [(size_t)BB*SS*UU];

__device__ bf16 g_xh   [(size_t)BB*SS*UU],   g_xl   [(size_t)BB*SS*UU];
__device__ bf16 g_fullh[(size_t)BB*KLEN*UU], g_fulll[(size_t)BB*KLEN*UU];
__device__ bf16 g_relh [(size_t)KLEN*UU],    g_rell [(size_t)KLEN*UU];
__device__ bf16 g_qch  [(size_t)BB*SS*UU],   g_qcl  [(size_t)BB*SS*UU];
__device__ bf16 g_qrh  [(size_t)BB*SS*UU],   g_qrl  [(size_t)BB*SS*UU];
__device__ bf16 g_kvh  [(size_t)BB*KLEN*2*UU], g_kvl [(size_t)BB*KLEN*2*UU];
__device__ bf16 g_rh   [(size_t)KLEN*UU],    g_rl   [(size_t)KLEN*UU];
__device__ bf16 g_ph   [(size_t)BB*HH*SS*KLEN], g_pl [(size_t)BB*HH*SS*KLEN];
__device__ bf16 g_vth  [(size_t)BB*HH*DD*KLEN], g_vtl[(size_t)BB*HH*DD*KLEN];
__device__ bf16 g_ctxh [(size_t)BB*SS*UU],   g_ctxl [(size_t)BB*SS*UU];
// fp16 buffers (FF + logits 2-pass paths)
__device__ __half g_h1hh[(size_t)BB*SS*UU],  g_h1lh [(size_t)BB*SS*UU];
__device__ __half g_ffhh[(size_t)BB*SS*FFD], g_fflh [(size_t)BB*SS*FFD];
__device__ __half g_h2hh[(size_t)BB*SS*UU],  g_h2lh [(size_t)BB*SS*UU];
__device__ __half g_W1H [(size_t)FFD*UU];
__device__ __half g_W2H [(size_t)UU*FFD];
__device__ __half g_WoutH[(size_t)NT*UU];
// transposed weights [N,K] bf16 hi/lo
__device__ bf16 g_WqTh [(size_t)UU*UU],    g_WqTl [(size_t)UU*UU];
__device__ bf16 g_WkvTh[(size_t)2*UU*UU],  g_WkvTl[(size_t)2*UU*UU];
__device__ bf16 g_WrTh [(size_t)UU*UU],    g_WrTl [(size_t)UU*UU];
__device__ bf16 g_WoTh [(size_t)UU*UU],    g_WoTl [(size_t)UU*UU];

// ---------------- helpers ----------------
__device__ __forceinline__ uint32_t smem_u32(const void* p) {
    uint32_t a;
    asm("{ .reg .u64 t; cvta.to.shared.u64 t, %1; cvt.u32.u64 %0, t; }" : "=r"(a) : "l"(p));
    return a;
}
__device__ __forceinline__ void split_to(float v, bf16& h, bf16& l) {
    h = __float2bfloat16(v);
    l = __float2bfloat16(v - __bfloat162float(h));
}
__device__ __forceinline__ void split_to(float v, __half& h, __half& l) {
    h = __float2half(v);
    l = __float2half(v - __half2float(h));
}
template<typename T>
__device__ __forceinline__ uint32_t pack2(T a, T b) {
    unsigned short x = *(unsigned short*)&a, y = *(unsigned short*)&b;
    return (uint32_t)x | ((uint32_t)y << 16);
}
__device__ __forceinline__ void cp16(uint32_t dst, const void* src) {
    asm volatile("cp.async.cg.shared.global [%0], [%1], 16;" :: "r"(dst), "l"(src));
}
__device__ __forceinline__ void ldx4(uint32_t* r, uint32_t addr) {
    asm volatile("ldmatrix.sync.aligned.m8n8.x4.shared.b16 {%0,%1,%2,%3}, [%4];"
                 : "=r"(r[0]), "=r"(r[1]), "=r"(r[2]), "=r"(r[3]) : "r"(addr));
}
__device__ __forceinline__ void mma_bf(float* c, const uint32_t* a, const uint32_t* b) {
    asm volatile("mma.sync.aligned.m16n8k16.row.col.f32.bf16.bf16.f32 "
                 "{%0,%1,%2,%3}, {%4,%5,%6,%7}, {%8,%9}, {%0,%1,%2,%3};"
                 : "+f"(c[0]), "+f"(c[1]), "+f"(c[2]), "+f"(c[3])
                 : "r"(a[0]), "r"(a[1]), "r"(a[2]), "r"(a[3]), "r"(b[0]), "r"(b[1]));
}
__device__ __forceinline__ void mma_fp(float* c, const uint32_t* a, const uint32_t* b) {
    asm volatile("mma.sync.aligned.m16n8k16.row.col.f32.f16.f16.f32 "
                 "{%0,%1,%2,%3}, {%4,%5,%6,%7}, {%8,%9}, {%0,%1,%2,%3};"
                 : "+f"(c[0]), "+f"(c[1]), "+f"(c[2]), "+f"(c[3])
                 : "r"(a[0]), "r"(a[1]), "r"(a[2]), "r"(a[3]), "r"(b[0]), "r"(b[1]));
}

template<int PASS> struct ETsel { typedef bf16 T; };
template<> struct ETsel<2> { typedef __half T; };

// ---------------- generalized HMMA split GEMM ----------------
// PASS=3 (bf16): C = (Ah+Al) @ (Bh+Bl)^T via hh + hl + lh.
// PASS=2 (fp16): C = (Ah+Al) @ Bh^T via hh + lh (Bl unused).
// 6-stage cp.async pipeline (3 groups of K32), ONE barrier per K32.
// maskA: if >=0, skip tile when n0 > m0 + maskA (causal dead tiles).
// maskB: if >=0, skip tile when m0 + n0 < maskB (rel-shift dead tiles).
// kclamp: if >=0, effective K = min(K, m0 + kclamp)  (must stay %32, >=64).
// OUT: 0 = fp32 C (+bias); 1 = split ET; 2 = relu + split ET; 3 = dual-bias split ET.
template<int BN, int OUT, int PASS>
__global__ __launch_bounds__(256)
void hgemm(const bf16* __restrict__ Ah, const bf16* __restrict__ Al,
           const bf16* __restrict__ Bh, const bf16* __restrict__ Bl,
           float* __restrict__ C, bf16* __restrict__ Chp, bf16* __restrict__ Clp,
           bf16* __restrict__ Dhp, bf16* __restrict__ Dlp,
           const float* __restrict__ bias,
           const float* __restrict__ bias2, const float* __restrict__ bias3,
           int M, int N, int K, int lda, int ldb, int ldc, int Z2,
           long long sA1, long long sA2, long long sB1, long long sB2,
           long long sC1, long long sC2,
           int maskA, int maskB, int kclamp)
{
    typedef typename ETsel<PASS>::T ET;
    constexpr int BSTR = BN * 32;
    constexpr int STAGE = 8192 + (PASS == 3 ? 2 : 1) * BSTR;
    constexpr int MT = (BN == 128) ? 4 : 2;
    extern __shared__ __align__(128) char sm[];
    const uint32_t smb = smem_u32(sm);
    const int tid = threadIdx.x, wid = tid >> 5, lane = tid & 31;
    const int m0 = blockIdx.x * 128, n0 = blockIdx.y * BN;
    if (maskA >= 0 && n0 > m0 + maskA) return;
    if (maskB >= 0 && m0 + n0 < maskB) return;
    const int Keff = (kclamp >= 0) ? min(K, m0 + kclamp) : K;

    const int m_w = (BN == 128) ? (wid & 1) * 64 : (wid & 3) * 32;
    const int n_w = (BN == 128) ? (wid >> 1) * 32 : (wid >> 2) * 32;

    const int z = blockIdx.z;
    const int z1 = z / Z2, z2 = z - z1 * Z2;
    Ah += z1 * sA1 + z2 * sA2;  Al += z1 * sA1 + z2 * sA2;
    Bh += z1 * sB1 + z2 * sB2;
    if (PASS == 3) Bl += z1 * sB1 + z2 * sB2;
    const long long cbase = z1 * sC1 + z2 * sC2;

    const int lr = tid >> 1, lc = tid & 1;
    const uint32_t so = (uint32_t)(lr * 32 + ((lc ^ ((lr >> 2) & 1)) << 4));
    const int ga = min(m0 + lr, M - 1);
    const long long aoff = (long long)ga * lda + lc * 8;
    const bool bdo = (BN == 128) || (tid < 128);
    const int gb = min(n0 + lr, N - 1);
    const long long boff = (long long)gb * ldb + lc * 8;

    float acc[MT][4][4];
    #pragma unroll
    for (int i = 0; i < MT; i++)
        #pragma unroll
        for (int j = 0; j < 4; j++)
            #pragma unroll
            for (int k = 0; k < 4; k++) acc[i][j][k] = 0.f;

    const int NC = Keff / 16;
    const int NP = NC / 2;

    // prologue: groups 0,1 (chunks 0..3; NC >= 4 at all call sites)
    #pragma unroll
    for (int g = 0; g < 2; g++) {
        #pragma unroll
        for (int s = 0; s < 2; s++) {
            const int ck = 2 * g + s;
            const uint32_t st = smb + (2 * g + s) * STAGE;
            cp16(st + so,        (const char*)Ah + (aoff + ck * 16) * 2);
            cp16(st + 4096 + so, (const char*)Al + (aoff + ck * 16) * 2);
            if (bdo) {
                cp16(st + 8192 + so, (const char*)Bh + (boff + ck * 16) * 2);
                if (PASS == 3) cp16(st + 8192 + BSTR + so, (const char*)Bl + (boff + ck * 16) * 2);
            }
        }
        asm volatile("cp.async.commit_group;");
    }

    const int rr = lane & 15, ccq = lane >> 4;
    const int rbq = (lane & 7) | ((lane & 16) >> 1);
    const int cbq = (lane >> 3) & 1;

    for (int p = 0; p < NP; p++) {
        asm volatile("cp.async.wait_group 1;");
        __syncthreads();
        // prefetch group p+2 into stage-block ((p+2)%3)*2
        {
            const int gidx = p + 2;
            const int sb = (gidx % 3) * 2;
            #pragma unroll
            for (int s = 0; s < 2; s++) {
                const int ck = 2 * gidx + s;
                if (ck < NC) {
                    const uint32_t st = smb + (sb + s) * STAGE;
                    cp16(st + so,        (const char*)Ah + (aoff + ck * 16) * 2);
                    cp16(st + 4096 + so, (const char*)Al + (aoff + ck * 16) * 2);
                    if (bdo) {
                        cp16(st + 8192 + so, (const char*)Bh + (boff + ck * 16) * 2);
                        if (PASS == 3) cp16(st + 8192 + BSTR + so, (const char*)Bl + (boff + ck * 16) * 2);
                    }
                }
            }
            asm volatile("cp.async.commit_group;");
        }
        // compute the 2 chunks of group p
        const int cb2 = (p % 3) * 2;
        #pragma unroll
        for (int s = 0; s < 2; s++) {
            const uint32_t st = smb + (cb2 + s) * STAGE;
            uint32_t ah[MT][4], al[MT][4], bh[2][4], bl[2][4];
            #pragma unroll
            for (int mt = 0; mt < MT; mt++) {
                int R = m_w + mt * 16 + rr;
                uint32_t ad = st + R * 32 + ((ccq ^ ((R >> 2) & 1)) << 4);
                ldx4(ah[mt], ad);
                ldx4(al[mt], ad + 4096);
            }
            #pragma unroll
            for (int np = 0; np < 2; np++) {
                int Nr = n_w + np * 16 + rbq;
                uint32_t bd = st + 8192 + Nr * 32 + ((cbq ^ ((Nr >> 2) & 1)) << 4);
                ldx4(bh[np], bd);
                if (PASS == 3) ldx4(bl[np], bd + BSTR);
            }
            #pragma unroll
            for (int mt = 0; mt < MT; mt++)
                #pragma unroll
                for (int nt = 0; nt < 4; nt++) {
                    const uint32_t* bhp = &bh[nt >> 1][(nt & 1) * 2];
                    if (PASS == 3) {
                        const uint32_t* blp = &bl[nt >> 1][(nt & 1) * 2];
                        mma_bf(acc[mt][nt], ah[mt], bhp);
                        mma_bf(acc[mt][nt], ah[mt], blp);
                        mma_bf(acc[mt][nt], al[mt], bhp);
                    } else {
                        mma_fp(acc[mt][nt], ah[mt], bhp);
                        mma_fp(acc[mt][nt], al[mt], bhp);
                    }
                }
        }
    }

    // ---- epilogue ----
    ET* Ch = (ET*)Chp; ET* Cl = (ET*)Clp;
    ET* Dh = (ET*)Dhp; ET* Dl = (ET*)Dlp;
    #pragma unroll
    for (int mt = 0; mt < MT; mt++) {
        int gm0 = m0 + m_w + mt * 16 + (lane >> 2);
        #pragma unroll
        for (int nt = 0; nt < 4; nt++) {
            int gn = n0 + n_w + nt * 8 + (lane & 3) * 2;
            if (gn >= N) continue;
            float bx = 0.f, by = 0.f;
            if (bias) { float2 bv = *(const float2*)(bias + gn); bx = bv.x; by = bv.y; }
            float v0 = acc[mt][nt][0] + bx;
            float v1 = acc[mt][nt][1] + by;
            float v2 = acc[mt][nt][2] + bx;
            float v3 = acc[mt][nt][3] + by;
            if (OUT == 0) {
                if (gm0 < M) {
                    float2 w; w.x = v0; w.y = v1;
                    *(float2*)(C + cbase + (long long)gm0 * ldc + gn) = w;
                }
                if (gm0 + 8 < M) {
                    float2 w; w.x = v2; w.y = v3;
                    *(float2*)(C + cbase + (long long)(gm0 + 8) * ldc + gn) = w;
                }
            } else if (OUT == 3) {
                float2 b2 = *(const float2*)(bias2 + gn);
                float2 b3 = *(const float2*)(bias3 + gn);
                ET h0, l0, h1, l1;
                if (gm0 < M) {
                    long long o = cbase + (long long)gm0 * ldc + gn;
                    split_to(v0 + b2.x, h0, l0); split_to(v1 + b2.y, h1, l1);
                    *(uint32_t*)(Ch + o) = pack2(h0, h1); *(uint32_t*)(Cl + o) = pack2(l0, l1);
                    split_to(v0 + b3.x, h0, l0); split_to(v1 + b3.y, h1, l1);
                    *(uint32_t*)(Dh + o) = pack2(h0, h1); *(uint32_t*)(Dl + o) = pack2(l0, l1);
                }
                if (gm0 + 8 < M) {
                    long long o = cbase + (long long)(gm0 + 8) * ldc + gn;
                    split_to(v2 + b2.x, h0, l0); split_to(v3 + b2.y, h1, l1);
                    *(uint32_t*)(Ch + o) = pack2(h0, h1); *(uint32_t*)(Cl + o) = pack2(l0, l1);
                    split_to(v2 + b3.x, h0, l0); split_to(v3 + b3.y, h1, l1);
                    *(uint32_t*)(Dh + o) = pack2(h0, h1); *(uint32_t*)(Dl + o) = pack2(l0, l1);
                }
            } else {
                if (OUT == 2) {
                    v0 = fmaxf(v0, 0.f); v1 = fmaxf(v1, 0.f);
                    v2 = fmaxf(v2, 0.f); v3 = fmaxf(v3, 0.f);
                }
                ET h0, l0, h1, l1;
                if (gm0 < M) {
                    long long o = cbase + (long long)gm0 * ldc + gn;
                    split_to(v0, h0, l0); split_to(v1, h1, l1);
                    *(uint32_t*)(Ch + o) = pack2(h0, h1); *(uint32_t*)(Cl + o) = pack2(l0, l1);
                }
                if (gm0 + 8 < M) {
                    long long o = cbase + (long long)(gm0 + 8) * ldc + gn;
                    split_to(v2, h0, l0); split_to(v3, h1, l1);
                    *(uint32_t*)(Ch + o) = pack2(h0, h1); *(uint32_t*)(Cl + o) = pack2(l0, l1);
                }
            }
        }
    }
}

// ---------------- reductions ----------------
__device__ __forceinline__ float block_reduce_sum(float v) {
    __shared__ float sm[16];
    __syncthreads();
    #pragma unroll
    for (int o = 16; o > 0; o >>= 1) v += __shfl_xor_sync(0xffffffffu, v, o);
    if ((threadIdx.x & 31) == 0) sm[threadIdx.x >> 5] = v;
    __syncthreads();
    if (threadIdx.x < 32) {
        float x = (threadIdx.x < (blockDim.x >> 5)) ? sm[threadIdx.x] : 0.f;
        #pragma unroll
        for (int o = 8; o > 0; o >>= 1) x += __shfl_xor_sync(0xffffffffu, x, o);
        if (threadIdx.x == 0) sm[0] = x;
    }
    __syncthreads();
    return sm[0];
}
__device__ __forceinline__ float block_reduce_max(float v) {
    __shared__ float sm[16];
    __syncthreads();
    #pragma unroll
    for (int o = 16; o > 0; o >>= 1) v = fmaxf(v, __shfl_xor_sync(0xffffffffu, v, o));
    if ((threadIdx.x & 31) == 0) sm[threadIdx.x >> 5] = v;
    __syncthreads();
    if (threadIdx.x < 32) {
        float x = (threadIdx.x < (blockDim.x >> 5)) ? sm[threadIdx.x] : -3.4e38f;
        #pragma unroll
        for (int o = 8; o > 0; o >>= 1) x = fmaxf(x, __shfl_xor_sync(0xffffffffu, x, o));
        if (threadIdx.x == 0) sm[0] = x;
    }
    __syncthreads();
    return sm[0];
}

// ---------------- small kernels ----------------
__global__ void build_full(const int* __restrict__ tokens,
                           const float* __restrict__ memory,
                           const float* __restrict__ embed,
                           float* __restrict__ x,
                           bf16* __restrict__ xh, bf16* __restrict__ xl,
                           bf16* __restrict__ fullh, bf16* __restrict__ fulll)
{
    long long idx = (long long)blockIdx.x * 256 + threadIdx.x;
    const long long tot = (long long)BB * KLEN * UU;
    if (idx >= tot) return;
    int u = (int)(idx % UU);
    long long t = idx / UU;
    int j = (int)(t % KLEN);
    int b = (int)(t / KLEN);
    float v;
    if (j < MEMLEN) {
        v = memory[((long long)b * MEMLEN + j) * UU + u];
    } else {
        int s = j - MEMLEN;
        int tok = tokens[b * SS + s];
        v = embed[(long long)tok * UU + u] * 32.0f;  // sqrt(1024)
        long long xo = ((long long)b * SS + s) * UU + u;
        x[xo] = v;
        bf16 h, l; split_to(v, h, l);
        xh[xo] = h; xl[xo] = l;
    }
    bf16 h, l; split_to(v, h, l);
    fullh[idx] = h; fulll[idx] = l;
}

__global__ void pos_embed(bf16* __restrict__ relh, bf16* __restrict__ rell)
{
    long long idx = (long long)blockIdx.x * 256 + threadIdx.x;
    if (idx >= (long long)KLEN * UU) return;
    int u = (int)(idx % UU);
    int jj = (int)(idx / UU);
    float pos = (float)(KLEN - 1 - jj);
    int i2 = (u < UU / 2) ? u : (u - UU / 2);
    float expo = ((float)(2 * i2)) / (float)UU;
    float invf = expf(-expo * 9.210340371976184f);  // ln(10000)
    float ang = pos * invf;
    float v = (u < UU / 2) ? sinf(ang) : cosf(ang);
    bf16 h, l; split_to(v, h, l);
    relh[idx] = h; rell[idx] = l;
}

// transpose + split: W[K,N] fp32 -> hi/lo[N,K] bf16
__global__ void split_T(const float* __restrict__ W, bf16* __restrict__ hi,
                        bf16* __restrict__ lo, int K, int N)
{
    __shared__ float t[32][33];
    int n0 = blockIdx.x * 32, k0 = blockIdx.y * 32;
    #pragma unroll
    for (int i = 0; i < 32; i += 8)
        t[threadIdx.y + i][threadIdx.x] =
            W[(long long)(k0 + threadIdx.y + i) * N + n0 + threadIdx.x];
    __syncthreads();
    #pragma unroll
    for (int i = 0; i < 32; i += 8) {
        float v = t[threadIdx.x][threadIdx.y + i];
        long long o = (long long)(n0 + threadIdx.y + i) * K + k0 + threadIdx.x;
        bf16 h, l; split_to(v, h, l);
        hi[o] = h; lo[o] = l;
    }
}

// transpose: W[K,N] fp32 -> single fp16 [N,K]
__global__ void split_T_h(const float* __restrict__ W, __half* __restrict__ hi,
                          int K, int N)
{
    __shared__ float t[32][33];
    int n0 = blockIdx.x * 32, k0 = blockIdx.y * 32;
    #pragma unroll
    for (int i = 0; i < 32; i += 8)
        t[threadIdx.y + i][threadIdx.x] =
            W[(long long)(k0 + threadIdx.y + i) * N + n0 + threadIdx.x];
    __syncthreads();
    #pragma unroll
    for (int i = 0; i < 32; i += 8) {
        float v = t[threadIdx.x][threadIdx.y + i];
        long long o = (long long)(n0 + threadIdx.y + i) * K + k0 + threadIdx.x;
        hi[o] = __float2half(v);
    }
}

// V^T per head: vt[(b*H+h), d, j] = kv[b, j, U + h*64 + d]
__global__ void transpose_v(const bf16* __restrict__ kvh, const bf16* __restrict__ kvl,
                            bf16* __restrict__ vth, bf16* __restrict__ vtl)
{
    __shared__ bf16 th[32][33], tl[32][33];
    int z = blockIdx.z;
    int b = z / HH, h = z % HH;
    int j0 = blockIdx.x * 32, d0 = blockIdx.y * 32;
    int tx = threadIdx.x, ty = threadIdx.y;
    #pragma unroll
    for (int i = 0; i < 32; i += 8) {
        long long src = ((long long)b * KLEN + j0 + ty + i) * (2 * UU) + UU + h * 64 + d0 + tx;
        th[ty + i][tx] = kvh[src];
        tl[ty + i][tx] = kvl[src];
    }
    __syncthreads();
    #pragma unroll
    for (int i = 0; i < 32; i += 8) {
        long long dst = ((long long)z * DD + d0 + ty + i) * KLEN + j0 + tx;
        vth[dst] = th[tx][ty + i];
        vtl[dst] = tl[tx][ty + i];
    }
}

// mask + rel-shift + softmax; writes P as split bf16 (zero tail)
__global__ __launch_bounds__(256)
void attn_softmax(const float* __restrict__ ac, const float* __restrict__ ar,
                  bf16* __restrict__ ph, bf16* __restrict__ pl)
{
    int i = blockIdx.x;
    long long z = blockIdx.y;
    const float* arow = ac + (z * SS + i) * (long long)KLEN;
    const float* rrow = ar + (z * SS + i) * (long long)KLEN;
    bf16* phr = ph + (z * SS + i) * (long long)KLEN;
    bf16* plr = pl + (z * SS + i) * (long long)KLEN;
    int lim = i + MEMLEN;
    int shift = SS - 1 - i;
    int tid = threadIdx.x;

    float vals[7];
    int cnt = 0;
    float lmax = -3.4e38f;
    for (int j = tid; j <= lim; j += 256) {
        float v = (arow[j] + rrow[j + shift]) * 0.125f;
        vals[cnt++] = v;
        lmax = fmaxf(lmax, v);
    }
    float m = block_reduce_max(lmax);
    float lsum = 0.f;
    for (int t = 0; t < cnt; t++) {
        float e = expf(vals[t] - m);
        vals[t] = e;
        lsum += e;
    }
    float s = block_reduce_sum(lsum);
    float inv = 1.f / s;
    cnt = 0;
    for (int j = tid; j <= lim; j += 256) {
        float p = vals[cnt++] * inv;
        bf16 h, l; split_to(p, h, l);
        phr[j] = h; plr[j] = l;
    }
    bf16 z0 = __float2bfloat16(0.f);
    for (int j = lim + 1 + tid; j < KLEN; j += 256) { phr[j] = z0; plr[j] = z0; }
}

// add + LayerNorm; emits fp32 (optional) plus split pair of type T
template<typename T>
__global__ __launch_bounds__(256)
void add_ln(const float* __restrict__ a, const float* __restrict__ b,
            const float* __restrict__ g, const float* __restrict__ beta,
            float* __restrict__ out, T* __restrict__ oh, T* __restrict__ ol)
{
    long long row = blockIdx.x;
    const float* pa = a + row * UU;
    const float* pb = b + row * UU;
    int tid = threadIdx.x;
    float vals[4];
    float s = 0.f, ss = 0.f;
    #pragma unroll
    for (int t = 0; t < 4; t++) {
        int idx = tid * 4 + t;
        float v = pa[idx] + pb[idx];
        vals[t] = v;
        s += v;
        ss += v * v;
    }
    s = block_reduce_sum(s);
    ss = block_reduce_sum(ss);
    float mean = s * (1.f / UU);
    float var = fmaxf(ss * (1.f / UU) - mean * mean, 0.f);
    float rstd = rsqrtf(var + 1e-5f);
    #pragma unroll
    for (int t = 0; t < 4; t++) {
        int idx = tid * 4 + t;
        float v = (vals[t] - mean) * rstd * g[idx] + beta[idx];
        if (out) out[row * UU + idx] = v;
        T h, l; split_to(v, h, l);
        oh[row * UU + idx] = h; ol[row * UU + idx] = l;
    }
}

// online-softmax over vocab rows, in place
__global__ __launch_bounds__(512)
void softmax_rows(float* __restrict__ x, int N)
{
    __shared__ float smm[16], sms[16];
    long long row = blockIdx.x;
    float* p = x + row * (long long)N;
    int tid = threadIdx.x;
    float m = -3.4e38f, s = 0.f;
    for (int j = tid; j < N; j += 512) {
        float v = p[j];
        if (v > m) { s = s * expf(m - v) + 1.f; m = v; }
        else       { s += expf(v - m); }
    }
    #pragma unroll
    for (int o = 16; o > 0; o >>= 1) {
        float m2 = __shfl_xor_sync(0xffffffffu, m, o);
        float s2 = __shfl_xor_sync(0xffffffffu, s, o);
        float M = fmaxf(m, m2);
        s = s * expf(m - M) + s2 * expf(m2 - M);
        m = M;
    }
    if ((tid & 31) == 0) { smm[tid >> 5] = m; sms[tid >> 5] = s; }
    __syncthreads();
    if (tid < 32) {
        float mm = (tid < 16) ? smm[tid] : -3.4e38f;
        float ssv = (tid < 16) ? sms[tid] : 0.f;
        #pragma unroll
        for (int o = 8; o > 0; o >>= 1) {
            float m2 = __shfl_xor_sync(0xffffffffu, mm, o);
            float s2 = __shfl_xor_sync(0xffffffffu, ssv, o);
            float M = fmaxf(mm, m2);
            ssv = ssv * expf(mm - M) + s2 * expf(m2 - M);
            mm = M;
        }
        if (tid == 0) { smm[0] = mm; sms[0] = ssv; }
    }
    __syncthreads();
    float M = smm[0];
    float inv = 1.f / sms[0];
    for (int j = tid; j < N; j += 512) p[j] = expf(p[j] - M) * inv;
}

// ---------------- host ----------------
#define SMEM6(BN, PASS) (6 * (8192 + ((PASS) == 3 ? 2 : 1) * (BN) * 32))

extern "C" void kernel_launch(void* const* d_in, const int* in_sizes, int n_in,
                              void* d_out, int out_size)
{
    const int*   tokens  = (const int*)  d_in[0];
    const float* memory  = (const float*)d_in[1];
    const float* embed   = (const float*)d_in[2];
    const float* Wq      = (const float*)d_in[3];
    const float* Wkv     = (const float*)d_in[4];
    const float* Wr      = (const float*)d_in[5];
    const float* Wo      = (const float*)d_in[6];
    const float* bq      = (const float*)d_in[7];
    const float* bkv     = (const float*)d_in[8];
    const float* br      = (const float*)d_in[9];
    const float* bo      = (const float*)d_in[10];
    const float* bias_c  = (const float*)d_in[11];
    const float* bias_r  = (const float*)d_in[12];
    const float* ln1_g   = (const float*)d_in[13];
    const float* ln1_b   = (const float*)d_in[14];
    const float* W1      = (const float*)d_in[15];
    const float* b1      = (const float*)d_in[16];
    const float* W2      = (const float*)d_in[17];
    const float* b2      = (const float*)d_in[18];
    const float* ln2_g   = (const float*)d_in[19];
    const float* ln2_b   = (const float*)d_in[20];
    const float* Wout    = (const float*)d_in[21];
    const float* bout    = (const float*)d_in[22];
    float* out = (float*)d_out;

    static bool s_attr = false;
    if (!s_attr) {
        cudaFuncSetAttribute(hgemm<128,0,3>, cudaFuncAttributeMaxDynamicSharedMemorySize, SMEM6(128,3));
        cudaFuncSetAttribute(hgemm<128,1,3>, cudaFuncAttributeMaxDynamicSharedMemorySize, SMEM6(128,3));
        cudaFuncSetAttribute(hgemm<128,3,3>, cudaFuncAttributeMaxDynamicSharedMemorySize, SMEM6(128,3));
        cudaFuncSetAttribute(hgemm<64,1,3>,  cudaFuncAttributeMaxDynamicSharedMemorySize, SMEM6(64,3));
        cudaFuncSetAttribute(hgemm<128,0,2>, cudaFuncAttributeMaxDynamicSharedMemorySize, SMEM6(128,2));
        cudaFuncSetAttribute(hgemm<128,2,2>, cudaFuncAttributeMaxDynamicSharedMemorySize, SMEM6(128,2));
        s_attr = true;
    }

    float *x, *ac, *ar, *tmp, *h1;
    cudaGetSymbolAddress((void**)&x,   g_x);
    cudaGetSymbolAddress((void**)&ac,  g_ac);
    cudaGetSymbolAddress((void**)&ar,  g_ar);
    cudaGetSymbolAddress((void**)&tmp, g_tmp);
    cudaGetSymbolAddress((void**)&h1,  g_h1);

    bf16 *xh,*xl,*fullh,*fulll,*relh,*rell;
    bf16 *qch,*qcl,*qrh,*qrl,*kvh,*kvl,*rh,*rl,*ph,*pl,*vth,*vtl,*ctxh,*ctxl;
    __half *h1hh,*h1lh,*ffhh,*fflh,*h2hh,*h2lh,*W1H,*W2H,*WoutH;
    cudaGetSymbolAddress((void**)&xh, g_xh);       cudaGetSymbolAddress((void**)&xl, g_xl);
    cudaGetSymbolAddress((void**)&fullh, g_fullh); cudaGetSymbolAddress((void**)&fulll, g_fulll);
    cudaGetSymbolAddress((void**)&relh, g_relh);   cudaGetSymbolAddress((void**)&rell, g_rell);
    cudaGetSymbolAddress((void**)&qch, g_qch);     cudaGetSymbolAddress((void**)&qcl, g_qcl);
    cudaGetSymbolAddress((void**)&qrh, g_qrh);     cudaGetSymbolAddress((void**)&qrl, g_qrl);
    cudaGetSymbolAddress((void**)&kvh, g_kvh);     cudaGetSymbolAddress((void**)&kvl, g_kvl);
    cudaGetSymbolAddress((void**)&rh, g_rh);       cudaGetSymbolAddress((void**)&rl, g_rl);
    cudaGetSymbolAddress((void**)&ph, g_ph);       cudaGetSymbolAddress((void**)&pl, g_pl);
    cudaGetSymbolAddress((void**)&vth, g_vth);     cudaGetSymbolAddress((void**)&vtl, g_vtl);
    cudaGetSymbolAddress((void**)&ctxh, g_ctxh);   cudaGetSymbolAddress((void**)&ctxl, g_ctxl);
    cudaGetSymbolAddress((void**)&h1hh, g_h1hh);   cudaGetSymbolAddress((void**)&h1lh, g_h1lh);
    cudaGetSymbolAddress((void**)&ffhh, g_ffhh);   cudaGetSymbolAddress((void**)&fflh, g_fflh);
    cudaGetSymbolAddress((void**)&h2hh, g_h2hh);   cudaGetSymbolAddress((void**)&h2lh, g_h2lh);
    cudaGetSymbolAddress((void**)&W1H, g_W1H);     cudaGetSymbolAddress((void**)&W2H, g_W2H);
    cudaGetSymbolAddress((void**)&WoutH, g_WoutH);

    bf16 *WqTh,*WqTl,*WkvTh,*WkvTl,*WrTh,*WrTl,*WoTh,*WoTl;
    cudaGetSymbolAddress((void**)&WqTh, g_WqTh);   cudaGetSymbolAddress((void**)&WqTl, g_WqTl);
    cudaGetSymbolAddress((void**)&WkvTh, g_WkvTh); cudaGetSymbolAddress((void**)&WkvTl, g_WkvTl);
    cudaGetSymbolAddress((void**)&WrTh, g_WrTh);   cudaGetSymbolAddress((void**)&WrTl, g_WrTl);
    cudaGetSymbolAddress((void**)&WoTh, g_WoTh);   cudaGetSymbolAddress((void**)&WoTl, g_WoTl);

    const int M_TOK = BB * SS;      // 2048
    const int M_FULL = BB * KLEN;   // 3200
    dim3 tb(32, 8);

    // 1) embedding + concat + splits
    {
        long long tot = (long long)BB * KLEN * UU;
        build_full<<<(unsigned)((tot + 255) / 256), 256>>>(tokens, memory, embed,
                                                           x, xh, xl, fullh, fulll);
    }
    // 2) Wkv split
    split_T<<<dim3(2*UU/32, UU/32), tb>>>(Wkv, WkvTh, WkvTl, UU, 2*UU);
    // 3) positional embedding
    {
        long long tot = (long long)KLEN * UU;
        pos_embed<<<(unsigned)((tot + 255) / 256), 256>>>(relh, rell);
    }
    // 4) kv projection  <-- ncu capture target (4th launch)
    hgemm<128,1,3><<<dim3((M_FULL+127)/128, 2*UU/128, 1), 256, SMEM6(128,3)>>>(
        fullh, fulll, WkvTh, WkvTl, nullptr, kvh, kvl, nullptr, nullptr, bkv, nullptr, nullptr,
        M_FULL, 2*UU, UU, UU, UU, 2*UU, 1, 0,0,0,0,0,0, -1,-1,-1);
    // remaining weight splits
    split_T<<<dim3(UU/32,  UU/32),  tb>>>(Wq,   WqTh,   WqTl,   UU,  UU);
    split_T<<<dim3(UU/32,  UU/32),  tb>>>(Wr,   WrTh,   WrTl,   UU,  UU);
    split_T<<<dim3(UU/32,  UU/32),  tb>>>(Wo,   WoTh,   WoTl,   UU,  UU);
    split_T_h<<<dim3(FFD/32, UU/32),  tb>>>(W1,   W1H,   UU,  FFD);
    split_T_h<<<dim3(UU/32,  FFD/32), tb>>>(W2,   W2H,   FFD, UU);
    split_T_h<<<dim3(NT/32,  UU/32),  tb>>>(Wout, WoutH, UU,  NT);
    // q projection fused with (q+u)/(q+v) splits
    hgemm<128,3,3><<<dim3(M_TOK/128, UU/128, 1), 256, SMEM6(128,3)>>>(
        xh, xl, WqTh, WqTl, nullptr, qch, qcl, qrh, qrl, bq, bias_c, bias_r,
        M_TOK, UU, UU, UU, UU, UU, 1, 0,0,0,0,0,0, -1,-1,-1);
    // r projection
    hgemm<128,1,3><<<dim3((KLEN+127)/128, UU/128, 1), 256, SMEM6(128,3)>>>(
        relh, rell, WrTh, WrTl, nullptr, rh, rl, nullptr, nullptr, br, nullptr, nullptr,
        KLEN, UU, UU, UU, UU, UU, 1, 0,0,0,0,0,0, -1,-1,-1);
    // scores (batched over b,h), with dead-tile skips
    {
        dim3 grid(SS / 128, (KLEN + 127) / 128, BB * HH);
        hgemm<128,0,3><<<grid, 256, SMEM6(128,3)>>>(qch, qcl, kvh, kvl, ac,
            nullptr, nullptr, nullptr, nullptr, nullptr, nullptr, nullptr,
            SS, KLEN, DD, UU, 2*UU, KLEN, HH,
            (long long)SS*UU, 64,
            (long long)KLEN*2*UU, 64,
            (long long)HH*SS*KLEN, (long long)SS*KLEN,
            MEMLEN + 127, -1, -1);                 // skip n0 > m0+703
        hgemm<128,0,3><<<grid, 256, SMEM6(128,3)>>>(qrh, qrl, rh, rl, ar,
            nullptr, nullptr, nullptr, nullptr, nullptr, nullptr, nullptr,
            SS, KLEN, DD, UU, UU, KLEN, HH,
            (long long)SS*UU, 64,
            0, 64,
            (long long)HH*SS*KLEN, (long long)SS*KLEN,
            -1, SS - 255, -1);                     // skip m0+n0 < 769
    }
    // fused rel-shift + mask + softmax -> split P
    {
        dim3 grid(SS, BB * HH);
        attn_softmax<<<grid, 256>>>(ac, ar, ph, pl);
    }
    // V^T per head
    {
        dim3 grid(KLEN / 32, DD / 32, BB * HH);
        transpose_v<<<grid, tb>>>(kvh, kvl, vth, vtl);
    }
    // ctx = P @ V^T (K clamped to m0+704: P zero beyond causal limit)
    {
        dim3 grid(SS / 128, 1, BB * HH);
        hgemm<64,1,3><<<grid, 256, SMEM6(64,3)>>>(ph, pl, vth, vtl, nullptr, ctxh, ctxl,
            nullptr, nullptr, nullptr, nullptr, nullptr,
            SS, DD, KLEN, KLEN, KLEN, UU, HH,
            (long long)HH*SS*KLEN, (long long)SS*KLEN,
            (long long)HH*DD*KLEN, (long long)DD*KLEN,
            (long long)SS*UU, 64,
            -1, -1, MEMLEN + 128);
    }
    // attention out projection + LN1 (fp16 splits for FF)
    hgemm<128,0,3><<<dim3(M_TOK/128, UU/128, 1), 256, SMEM6(128,3)>>>(
        ctxh, ctxl, WoTh, WoTl, tmp, nullptr, nullptr, nullptr, nullptr, bo, nullptr, nullptr,
        M_TOK, UU, UU, UU, UU, UU, 1, 0,0,0,0,0,0, -1,-1,-1);
    add_ln<__half><<<M_TOK, 256>>>(x, tmp, ln1_g, ln1_b, h1, h1hh, h1lh);
    // FF (fp16 2-pass)
    hgemm<128,2,2><<<dim3(M_TOK/128, FFD/128, 1), 256, SMEM6(128,2)>>>(
        (const bf16*)h1hh, (const bf16*)h1lh, (const bf16*)W1H, nullptr,
        nullptr, (bf16*)ffhh, (bf16*)fflh, nullptr, nullptr, b1, nullptr, nullptr,
        M_TOK, FFD, UU, UU, UU, FFD, 1, 0,0,0,0,0,0, -1,-1,-1);
    hgemm<128,0,2><<<dim3(M_TOK/128, UU/128, 1), 256, SMEM6(128,2)>>>(
        (const bf16*)ffhh, (const bf16*)fflh, (const bf16*)W2H, nullptr,
        tmp, nullptr, nullptr, nullptr, nullptr, b2, nullptr, nullptr,
        M_TOK, UU, FFD, FFD, FFD, UU, 1, 0,0,0,0,0,0, -1,-1,-1);
    // LN2 emits fp16 hi/lo for the 2-pass logits GEMM
    add_ln<__half><<<M_TOK, 256>>>(h1, tmp, ln2_g, ln2_b, nullptr, h2hh, h2lh);
    // logits: fp16 2-pass
    hgemm<128,0,2><<<dim3(M_TOK/128, NT/128, 1), 256, SMEM6(128,2)>>>(
        (const bf16*)h2hh, (const bf16*)h2lh, (const bf16*)WoutH, nullptr,
        out, nullptr, nullptr, nullptr, nullptr, bout, nullptr, nullptr,
        M_TOK, NT, UU, UU, UU, NT, 1, 0,0,0,0,0,0, -1,-1,-1);
    softmax_rows<<<M_TOK, 512>>>(out, NT);
}